// round 1
// baseline (speedup 1.0000x reference)
#include <cuda_runtime.h>
#include <math.h>

// Problem dims
#define NB   8
#define NT   2048
#define NC   768
#define NE   8
#define NKT  2      // top-k
#define NH   3072
#define NCAP 640
#define NM   (NB * NCAP)   // 5120 rows per expert

// ---------------- scratch (device globals; no allocation allowed) ----------
__device__ float g_act[(size_t)NE * NM * NH];   // post-silu activations  (~503MB)
__device__ float g_o  [(size_t)NE * NM * NC];   // expert outputs         (~126MB)
__device__ float g_p  [NB * NT * NKT];          // top-k probs
__device__ int   g_ei [NB * NT * NKT];          // top-k expert indices
__device__ int   g_pos[NB * NT * NKT];          // capacity slot (unclamped)
__device__ int   g_src[NE * NM];                // token source per (e, b*CAP+pos), -1 empty

// ---------------- kernel 1: router (logits -> softmax -> top2) -------------
__global__ void router_kernel(const float* __restrict__ x,
                              const float* __restrict__ wr,
                              const float* __restrict__ br) {
    __shared__ float ws[NC * NE];   // 24KB
    int tid = threadIdx.x;
    const float4* wr4 = (const float4*)wr;
    float4* ws4 = (float4*)ws;
    #pragma unroll
    for (int i = tid; i < NC * NE / 4; i += 256) ws4[i] = wr4[i];
    __syncthreads();

    int warp = tid >> 5, lane = tid & 31;
    int token = blockIdx.x * 8 + warp;        // grid = NB*NT/8
    const float* xrow = x + (size_t)token * NC;

    float acc[NE];
    #pragma unroll
    for (int e = 0; e < NE; e++) acc[e] = 0.f;

    for (int c = lane; c < NC; c += 32) {
        float xv = xrow[c];
        #pragma unroll
        for (int e = 0; e < NE; e++) acc[e] = fmaf(xv, ws[c * NE + e], acc[e]);
    }
    #pragma unroll
    for (int e = 0; e < NE; e++) {
        #pragma unroll
        for (int off = 16; off; off >>= 1)
            acc[e] += __shfl_xor_sync(0xffffffffu, acc[e], off);
    }

    if (lane == 0) {
        float l[NE], p[NE];
        float mx = -1e30f;
        #pragma unroll
        for (int e = 0; e < NE; e++) { l[e] = acc[e] + br[e]; mx = fmaxf(mx, l[e]); }
        float s = 0.f;
        #pragma unroll
        for (int e = 0; e < NE; e++) { p[e] = expf(l[e] - mx); s += p[e]; }
        float inv = 1.f / s;
        #pragma unroll
        for (int e = 0; e < NE; e++) p[e] *= inv;

        // top-2, lowest index wins ties (strict >), matching lax.top_k
        int i1 = 0; float p1 = p[0];
        #pragma unroll
        for (int e = 1; e < NE; e++) if (p[e] > p1) { p1 = p[e]; i1 = e; }
        int i2 = -1; float p2 = -1.f;
        #pragma unroll
        for (int e = 0; e < NE; e++) if (e != i1 && p[e] > p2) { p2 = p[e]; i2 = e; }

        g_p [token * 2 + 0] = p1;  g_p [token * 2 + 1] = p2;
        g_ei[token * 2 + 0] = i1;  g_ei[token * 2 + 1] = i2;
    }
}

// ---------------- kernel 2: clear src table ---------------------------------
__global__ void fill_src_kernel() {
    int i = blockIdx.x * 256 + threadIdx.x;
    if (i < NE * NM) g_src[i] = -1;
}

// ---------------- kernel 3: capacity scan (k-major, t order) per batch ------
// one warp per batch; exact cumsum order of the reference
__global__ void pos_kernel() {
    __shared__ int cnt[8][NE];
    int w = threadIdx.x >> 5, lane = threadIdx.x & 31;
    int b = w;
    if (lane < NE) cnt[w][lane] = 0;
    __syncwarp();

    for (int k = 0; k < NKT; k++) {
        for (int t0 = 0; t0 < NT; t0 += 32) {
            int t = t0 + lane;
            int e = g_ei[(b * NT + t) * NKT + k];
            unsigned mask = __match_any_sync(0xffffffffu, e);
            int prefix = __popc(mask & ((1u << lane) - 1u));
            int base = cnt[w][e];
            __syncwarp();
            int pos = base + prefix;
            g_pos[(b * NT + t) * NKT + k] = pos;
            if (pos < NCAP) g_src[e * NM + b * NCAP + pos] = b * NT + t;
            if (lane == (31 - __clz(mask))) cnt[w][e] = base + __popc(mask);
            __syncwarp();
        }
    }
}

// ---------------- kernel 4: fused FC + GATE GEMM + silu(h*g) ----------------
// X_e [5120 x 768] (gathered) @ Wfc/Wg [768 x 3072] -> act [5120 x 3072]
#define BM 128
#define BN 64
#define BK 16

__global__ __launch_bounds__(256, 2) void mlp1_kernel(
    const float* __restrict__ x,
    const float* __restrict__ w_fc, const float* __restrict__ b_fc,
    const float* __restrict__ w_g,  const float* __restrict__ b_g) {

    __shared__ float As[2][BK][BM];
    __shared__ float Bf[2][BK][BN];
    __shared__ float Bg[2][BK][BN];
    __shared__ int   s_src[BM];

    const int e  = blockIdx.z;
    const int m0 = blockIdx.y * BM;
    const int n0 = blockIdx.x * BN;
    const int tid = threadIdx.x;

    if (tid < BM) s_src[tid] = g_src[e * NM + m0 + tid];
    __syncthreads();

    const float* wfc = w_fc + (size_t)e * NC * NH;
    const float* wg  = w_g  + (size_t)e * NC * NH;

    const int tx = tid & 15, ty = tid >> 4;
    const int bk = tid >> 4, bn = (tid & 15) << 2;

    float acc_h[8][4], acc_g[8][4];
    #pragma unroll
    for (int i = 0; i < 8; i++)
        #pragma unroll
        for (int j = 0; j < 4; j++) { acc_h[i][j] = 0.f; acc_g[i][j] = 0.f; }

    float4 va[2]; float4 vbf, vbg;
    int am[2], ak[2];
    #pragma unroll
    for (int j = 0; j < 2; j++) {
        int i = tid * 2 + j;
        am[j] = i >> 2; ak[j] = (i & 3) << 2;
    }

    auto load_regs = [&](int kt) {
        int k0 = kt * BK;
        #pragma unroll
        for (int j = 0; j < 2; j++) {
            int row = s_src[am[j]];
            va[j] = (row >= 0)
                ? *(const float4*)(x + (size_t)row * NC + k0 + ak[j])
                : make_float4(0.f, 0.f, 0.f, 0.f);
        }
        vbf = *(const float4*)(wfc + (size_t)(k0 + bk) * NH + n0 + bn);
        vbg = *(const float4*)(wg  + (size_t)(k0 + bk) * NH + n0 + bn);
    };
    auto store_stage = [&](int buf) {
        #pragma unroll
        for (int j = 0; j < 2; j++) {
            As[buf][ak[j] + 0][am[j]] = va[j].x;
            As[buf][ak[j] + 1][am[j]] = va[j].y;
            As[buf][ak[j] + 2][am[j]] = va[j].z;
            As[buf][ak[j] + 3][am[j]] = va[j].w;
        }
        *(float4*)&Bf[buf][bk][bn] = vbf;
        *(float4*)&Bg[buf][bk][bn] = vbg;
    };
    auto compute_stage = [&](int buf) {
        #pragma unroll
        for (int k = 0; k < BK; k++) {
            float4 a0 = *(const float4*)&As[buf][k][ty * 8];
            float4 a1 = *(const float4*)&As[buf][k][ty * 8 + 4];
            float4 f4 = *(const float4*)&Bf[buf][k][tx * 4];
            float4 g4 = *(const float4*)&Bg[buf][k][tx * 4];
            float a[8] = {a0.x, a0.y, a0.z, a0.w, a1.x, a1.y, a1.z, a1.w};
            float fb[4] = {f4.x, f4.y, f4.z, f4.w};
            float gb[4] = {g4.x, g4.y, g4.z, g4.w};
            #pragma unroll
            for (int i = 0; i < 8; i++)
                #pragma unroll
                for (int j = 0; j < 4; j++) {
                    acc_h[i][j] = fmaf(a[i], fb[j], acc_h[i][j]);
                    acc_g[i][j] = fmaf(a[i], gb[j], acc_g[i][j]);
                }
        }
    };

    const int NSTG = NC / BK;  // 48
    load_regs(0);
    store_stage(0);
    __syncthreads();
    for (int kt = 0; kt < NSTG; kt++) {
        int cur = kt & 1;
        if (kt + 1 < NSTG) load_regs(kt + 1);
        compute_stage(cur);
        if (kt + 1 < NSTG) {
            __syncthreads();
            store_stage(cur ^ 1);
            __syncthreads();
        }
    }

    // epilogue: h = acc_h + bfc; g = acc_g + bg; act = silu(h*g)
    float4 bfc4 = *(const float4*)(b_fc + e * NH + n0 + tx * 4);
    float4 bg4  = *(const float4*)(b_g  + e * NH + n0 + tx * 4);
    float bfc[4] = {bfc4.x, bfc4.y, bfc4.z, bfc4.w};
    float bgg[4] = {bg4.x, bg4.y, bg4.z, bg4.w};

    #pragma unroll
    for (int i = 0; i < 8; i++) {
        int m = m0 + ty * 8 + i;
        float4 o;
        float* op = (float*)&o;
        #pragma unroll
        for (int j = 0; j < 4; j++) {
            float h = acc_h[i][j] + bfc[j];
            float g = acc_g[i][j] + bgg[j];
            float z = h * g;
            op[j] = z / (1.f + expf(-z));   // silu
        }
        *(float4*)(g_act + ((size_t)e * NM + m) * NH + n0 + tx * 4) = o;
    }
}

// ---------------- kernel 5: PROJ GEMM ---------------------------------------
// act [5120 x 3072] @ Wp [3072 x 768] -> o [5120 x 768]
#define BN2 128

__global__ __launch_bounds__(256, 2) void mlp2_kernel(
    const float* __restrict__ wp, const float* __restrict__ bp) {

    __shared__ float As[2][BK][BM];
    __shared__ float Bs[2][BK][BN2];

    const int e  = blockIdx.z;
    const int m0 = blockIdx.y * BM;
    const int n0 = blockIdx.x * BN2;
    const int tid = threadIdx.x;

    const float* wpe = wp + (size_t)e * NH * NC;
    const float* ape = g_act + (size_t)e * NM * NH;

    const int tx = tid & 15, ty = tid >> 4;

    float acc[8][8];
    #pragma unroll
    for (int i = 0; i < 8; i++)
        #pragma unroll
        for (int j = 0; j < 8; j++) acc[i][j] = 0.f;

    float4 va[2], vb[2];
    int am[2], ak[2], bkk[2], bnn[2];
    #pragma unroll
    for (int j = 0; j < 2; j++) {
        int i = tid * 2 + j;
        am[j] = i >> 2;        ak[j]  = (i & 3) << 2;
        bkk[j] = i >> 5;       bnn[j] = (i & 31) << 2;
    }

    auto load_regs = [&](int kt) {
        int k0 = kt * BK;
        #pragma unroll
        for (int j = 0; j < 2; j++) {
            va[j] = *(const float4*)(ape + (size_t)(m0 + am[j]) * NH + k0 + ak[j]);
            vb[j] = *(const float4*)(wpe + (size_t)(k0 + bkk[j]) * NC + n0 + bnn[j]);
        }
    };
    auto store_stage = [&](int buf) {
        #pragma unroll
        for (int j = 0; j < 2; j++) {
            As[buf][ak[j] + 0][am[j]] = va[j].x;
            As[buf][ak[j] + 1][am[j]] = va[j].y;
            As[buf][ak[j] + 2][am[j]] = va[j].z;
            As[buf][ak[j] + 3][am[j]] = va[j].w;
            *(float4*)&Bs[buf][bkk[j]][bnn[j]] = vb[j];
        }
    };
    auto compute_stage = [&](int buf) {
        #pragma unroll
        for (int k = 0; k < BK; k++) {
            float4 a0 = *(const float4*)&As[buf][k][ty * 8];
            float4 a1 = *(const float4*)&As[buf][k][ty * 8 + 4];
            float4 b0 = *(const float4*)&Bs[buf][k][tx * 8];
            float4 b1 = *(const float4*)&Bs[buf][k][tx * 8 + 4];
            float a[8] = {a0.x, a0.y, a0.z, a0.w, a1.x, a1.y, a1.z, a1.w};
            float b[8] = {b0.x, b0.y, b0.z, b0.w, b1.x, b1.y, b1.z, b1.w};
            #pragma unroll
            for (int i = 0; i < 8; i++)
                #pragma unroll
                for (int j = 0; j < 8; j++)
                    acc[i][j] = fmaf(a[i], b[j], acc[i][j]);
        }
    };

    const int NSTG = NH / BK;  // 192
    load_regs(0);
    store_stage(0);
    __syncthreads();
    for (int kt = 0; kt < NSTG; kt++) {
        int cur = kt & 1;
        if (kt + 1 < NSTG) load_regs(kt + 1);
        compute_stage(cur);
        if (kt + 1 < NSTG) {
            __syncthreads();
            store_stage(cur ^ 1);
            __syncthreads();
        }
    }

    float4 bp0 = *(const float4*)(bp + e * NC + n0 + tx * 8);
    float4 bp1 = *(const float4*)(bp + e * NC + n0 + tx * 8 + 4);
    float bb[8] = {bp0.x, bp0.y, bp0.z, bp0.w, bp1.x, bp1.y, bp1.z, bp1.w};

    #pragma unroll
    for (int i = 0; i < 8; i++) {
        int m = m0 + ty * 8 + i;
        float4 o0, o1;
        float* p0 = (float*)&o0; float* p1 = (float*)&o1;
        #pragma unroll
        for (int j = 0; j < 4; j++) { p0[j] = acc[i][j] + bb[j]; p1[j] = acc[i][j + 4] + bb[j + 4]; }
        float* dst = g_o + ((size_t)e * NM + m) * NC + n0 + tx * 8;
        *(float4*)dst = o0;
        *(float4*)(dst + 4) = o1;
    }
}

// ---------------- kernel 6: combine (clamped gather + weighted sum) ---------
__global__ void combine_kernel(float* __restrict__ out) {
    int token = blockIdx.x;           // b*NT + t
    int b = token / NT;

    int e0 = g_ei[token * 2 + 0], e1 = g_ei[token * 2 + 1];
    float p0 = g_p[token * 2 + 0], p1 = g_p[token * 2 + 1];
    int q0 = min(g_pos[token * 2 + 0], NCAP - 1);   // XLA gather clamps OOB reads
    int q1 = min(g_pos[token * 2 + 1], NCAP - 1);

    const float4* r0 = (const float4*)(g_o + ((size_t)e0 * NM + b * NCAP + q0) * NC);
    const float4* r1 = (const float4*)(g_o + ((size_t)e1 * NM + b * NCAP + q1) * NC);

    int c = threadIdx.x;              // 192 threads, float4 each
    float4 v0 = r0[c], v1 = r1[c];
    float4 o;
    o.x = p0 * v0.x + p1 * v1.x;
    o.y = p0 * v0.y + p1 * v1.y;
    o.z = p0 * v0.z + p1 * v1.z;
    o.w = p0 * v0.w + p1 * v1.w;
    ((float4*)out)[(size_t)token * (NC / 4) + c] = o;
}

// ---------------- launch ------------------------------------------------------
extern "C" void kernel_launch(void* const* d_in, const int* in_sizes, int n_in,
                              void* d_out, int out_size) {
    const float* x        = (const float*)d_in[0];
    const float* w_router = (const float*)d_in[1];
    const float* b_router = (const float*)d_in[2];
    const float* w_c_fc   = (const float*)d_in[3];
    const float* b_c_fc   = (const float*)d_in[4];
    const float* w_gate   = (const float*)d_in[5];
    const float* b_gate   = (const float*)d_in[6];
    const float* w_c_proj = (const float*)d_in[7];
    const float* b_c_proj = (const float*)d_in[8];
    float* out = (float*)d_out;

    router_kernel<<<NB * NT / 8, 256>>>(x, w_router, b_router);
    fill_src_kernel<<<(NE * NM + 255) / 256, 256>>>();
    pos_kernel<<<1, 256>>>();
    mlp1_kernel<<<dim3(NH / BN, NM / BM, NE), 256>>>(x, w_c_fc, b_c_fc, w_gate, b_gate);
    mlp2_kernel<<<dim3(NC / BN2, NM / BM, NE), 256>>>(w_c_proj, b_c_proj);
    combine_kernel<<<NB * NT, 192>>>(out);
}

// round 5
// speedup vs baseline: 1.9517x; 1.9517x over previous
#include <cuda_runtime.h>
#include <cuda_bf16.h>
#include <math.h>
#include <stdint.h>

// ---------------------------------------------------------------- dims
#define NB   8
#define NT   2048
#define NC   768
#define NE   8
#define NKT  2
#define NH   3072
#define NCAP 640
#define NM   (NB * NCAP)   // 5120 rows per expert

// ---------------------------------------------------------------- helpers
__device__ __forceinline__ uint32_t smem_u32(const void* p) {
    uint32_t a;
    asm("{ .reg .u64 t; cvta.to.shared.u64 t, %1; cvt.u32.u64 %0, t; }"
        : "=r"(a) : "l"(p));
    return a;
}
__device__ __forceinline__ void ldsm4(uint32_t* r, uint32_t a) {
    asm volatile("ldmatrix.sync.aligned.m8n8.x4.shared.b16 {%0,%1,%2,%3}, [%4];"
        : "=r"(r[0]), "=r"(r[1]), "=r"(r[2]), "=r"(r[3]) : "r"(a));
}
__device__ __forceinline__ void ldsm4t(uint32_t* r, uint32_t a) {
    asm volatile("ldmatrix.sync.aligned.m8n8.x4.trans.shared.b16 {%0,%1,%2,%3}, [%4];"
        : "=r"(r[0]), "=r"(r[1]), "=r"(r[2]), "=r"(r[3]) : "r"(a));
}
__device__ __forceinline__ void mma_bf16(float* d, const uint32_t* a, const uint32_t* b) {
    asm volatile(
        "mma.sync.aligned.m16n8k16.row.col.f32.bf16.bf16.f32 "
        "{%0,%1,%2,%3}, {%4,%5,%6,%7}, {%8,%9}, {%0,%1,%2,%3};"
        : "+f"(d[0]), "+f"(d[1]), "+f"(d[2]), "+f"(d[3])
        : "r"(a[0]), "r"(a[1]), "r"(a[2]), "r"(a[3]), "r"(b[0]), "r"(b[1]));
}
// split float4 into packed bf16 hi (uint2) and lo residual (uint2)
__device__ __forceinline__ void split4(float4 v, uint2& h, uint2& l) {
    __nv_bfloat16 h0 = __float2bfloat16(v.x), h1 = __float2bfloat16(v.y);
    __nv_bfloat16 h2 = __float2bfloat16(v.z), h3 = __float2bfloat16(v.w);
    float r0 = v.x - __bfloat162float(h0), r1 = v.y - __bfloat162float(h1);
    float r2 = v.z - __bfloat162float(h2), r3 = v.w - __bfloat162float(h3);
    h.x = (uint32_t)__bfloat16_as_ushort(h0) | ((uint32_t)__bfloat16_as_ushort(h1) << 16);
    h.y = (uint32_t)__bfloat16_as_ushort(h2) | ((uint32_t)__bfloat16_as_ushort(h3) << 16);
    l.x = (uint32_t)__bfloat16_as_ushort(__float2bfloat16(r0))
        | ((uint32_t)__bfloat16_as_ushort(__float2bfloat16(r1)) << 16);
    l.y = (uint32_t)__bfloat16_as_ushort(__float2bfloat16(r2))
        | ((uint32_t)__bfloat16_as_ushort(__float2bfloat16(r3)) << 16);
}

// ---------------------------------------------------------------- scratch (same set as passing R1)
__device__ float g_act[(size_t)NE * NM * NH];   // post-silu activations (fp32)
__device__ float g_o  [(size_t)NE * NM * NC];   // expert outputs
__device__ float g_p  [NB * NT * NKT];
__device__ int   g_ei [NB * NT * NKT];
__device__ int   g_pos[NB * NT * NKT];
__device__ int   g_src[NE * NM];

// ---------------------------------------------------------------- router (unchanged, passing)
__global__ void router_kernel(const float* __restrict__ x,
                              const float* __restrict__ wr,
                              const float* __restrict__ br) {
    __shared__ float ws[NC * NE];
    int tid = threadIdx.x;
    const float4* wr4 = (const float4*)wr;
    float4* ws4 = (float4*)ws;
    #pragma unroll
    for (int i = tid; i < NC * NE / 4; i += 256) ws4[i] = wr4[i];
    __syncthreads();

    int warp = tid >> 5, lane = tid & 31;
    int token = blockIdx.x * 8 + warp;
    const float* xrow = x + (size_t)token * NC;

    float acc[NE];
    #pragma unroll
    for (int e = 0; e < NE; e++) acc[e] = 0.f;
    for (int c = lane; c < NC; c += 32) {
        float xv = xrow[c];
        #pragma unroll
        for (int e = 0; e < NE; e++) acc[e] = fmaf(xv, ws[c * NE + e], acc[e]);
    }
    #pragma unroll
    for (int e = 0; e < NE; e++) {
        #pragma unroll
        for (int off = 16; off; off >>= 1)
            acc[e] += __shfl_xor_sync(0xffffffffu, acc[e], off);
    }
    if (lane == 0) {
        float l[NE], p[NE];
        float mx = -1e30f;
        #pragma unroll
        for (int e = 0; e < NE; e++) { l[e] = acc[e] + br[e]; mx = fmaxf(mx, l[e]); }
        float s = 0.f;
        #pragma unroll
        for (int e = 0; e < NE; e++) { p[e] = expf(l[e] - mx); s += p[e]; }
        float inv = 1.f / s;
        #pragma unroll
        for (int e = 0; e < NE; e++) p[e] *= inv;

        int i1 = 0; float p1 = p[0];
        #pragma unroll
        for (int e = 1; e < NE; e++) if (p[e] > p1) { p1 = p[e]; i1 = e; }
        int i2 = -1; float p2 = -1.f;
        #pragma unroll
        for (int e = 0; e < NE; e++) if (e != i1 && p[e] > p2) { p2 = p[e]; i2 = e; }

        g_p [token * 2 + 0] = p1;  g_p [token * 2 + 1] = p2;
        g_ei[token * 2 + 0] = i1;  g_ei[token * 2 + 1] = i2;
    }
}

__global__ void fill_src_kernel() {
    int i = blockIdx.x * 256 + threadIdx.x;
    if (i < NE * NM) g_src[i] = -1;
}

// capacity scan, exact k-major cumsum order per batch (unchanged, passing)
__global__ void pos_kernel() {
    __shared__ int cnt[8][NE];
    int w = threadIdx.x >> 5, lane = threadIdx.x & 31;
    int b = w;
    if (lane < NE) cnt[w][lane] = 0;
    __syncwarp();
    for (int k = 0; k < NKT; k++) {
        for (int t0 = 0; t0 < NT; t0 += 32) {
            int t = t0 + lane;
            int e = g_ei[(b * NT + t) * NKT + k];
            unsigned mask = __match_any_sync(0xffffffffu, e);
            int prefix = __popc(mask & ((1u << lane) - 1u));
            int base = cnt[w][e];
            __syncwarp();
            int pos = base + prefix;
            g_pos[(b * NT + t) * NKT + k] = pos;
            if (pos < NCAP) g_src[e * NM + b * NCAP + pos] = b * NT + t;
            if (lane == (31 - __clz(mask))) cnt[w][e] = base + __popc(mask);
            __syncwarp();
        }
    }
}

// ---------------------------------------------------------------- mlp1 (HMMA, hi/lo compensated)
// CTA tile M=128, N=64 (of H), K-step 32, single-buffered static smem.
// A regions: [128 rows][stride 80B] (32 halves data): A_H @0, A_L @10240
// B regions: [32 k-rows][stride 144B] (64 halves data): F_H @20480, F_L @25088,
//            G_H @29696, G_L @34304.  total 38912 B
#define M1_AH 0
#define M1_AL 10240
#define M1_FH 20480
#define M1_FL 25088
#define M1_GH 29696
#define M1_GL 34304

__global__ void __launch_bounds__(256) mlp1_kernel(const float* __restrict__ x,
                                                   const float* __restrict__ wfc,
                                                   const float* __restrict__ bfc,
                                                   const float* __restrict__ wgt,
                                                   const float* __restrict__ bgt) {
    __shared__ __align__(16) unsigned char SM[38912];
    __shared__ int s_src[128];
    const uint32_t sb = smem_u32(SM);
    const int tid = threadIdx.x;
    const int e = blockIdx.z;
    const int n0 = blockIdx.x * 64, m0 = blockIdx.y * 128;

    if (tid < 128) s_src[tid] = g_src[e * NM + m0 + tid];
    __syncthreads();

    const float* Wf = wfc + (size_t)e * NC * NH;   // [K=768][N=3072]
    const float* Wg = wgt + (size_t)e * NC * NH;

    const int wid = tid >> 5, lane = tid & 31;
    const int mwarp = wid >> 1, nwarp = wid & 1;   // 4 x 2 warps
    // A (row-major) ldmatrix address
    const uint32_t a_off = (uint32_t)(mwarp * 32 + (lane & 15)) * 80 + ((lane & 16) ? 16 : 0);
    // B (k-major, trans) ldmatrix address: lane&15 -> k-row, lane&16 -> +8 n cols
    const uint32_t bt_off = (uint32_t)(lane & 15) * 144 + ((lane & 16) ? 16 : 0) + nwarp * 64;

    float acch[2][4][4] = {};
    float accg[2][4][4] = {};

    const int NS = NC / 32;   // 24
    for (int s = 0; s < NS; s++) {
        const int k0 = s * 32;
        __syncthreads();
        // ---- fill A (gathered x rows, split hi/lo): 128 rows x 8 float4 chunks
        #pragma unroll
        for (int i = 0; i < 4; i++) {
            int j = tid + i * 256;            // 0..1023
            int r = j >> 3, ch = j & 7;       // row, 4-float chunk
            int srow = s_src[r];
            float4 v = (srow >= 0)
                ? *(const float4*)(x + (size_t)srow * NC + k0 + ch * 4)
                : make_float4(0.f, 0.f, 0.f, 0.f);
            uint2 h, l;
            split4(v, h, l);
            uint32_t d = (uint32_t)r * 80 + ch * 8;
            *(uint2*)(SM + M1_AH + d) = h;
            *(uint2*)(SM + M1_AL + d) = l;
        }
        // ---- fill B (fc + gate weights, k-major, split hi/lo): 32 rows x 16 chunks
        #pragma unroll
        for (int i = 0; i < 2; i++) {
            int j = tid + i * 256;            // 0..511
            int r = j >> 4, ch = j & 15;      // k-row, 4-float chunk along n
            size_t goff = (size_t)(k0 + r) * NH + n0 + ch * 4;
            float4 vf = *(const float4*)(Wf + goff);
            float4 vg = *(const float4*)(Wg + goff);
            uint2 fh, fl, gh, gl;
            split4(vf, fh, fl);
            split4(vg, gh, gl);
            uint32_t d = (uint32_t)r * 144 + ch * 8;
            *(uint2*)(SM + M1_FH + d) = fh;
            *(uint2*)(SM + M1_FL + d) = fl;
            *(uint2*)(SM + M1_GH + d) = gh;
            *(uint2*)(SM + M1_GL + d) = gl;
        }
        __syncthreads();

        #pragma unroll
        for (int ks = 0; ks < 2; ks++) {
            uint32_t ah[2][4], al[2][4];
            #pragma unroll
            for (int mt = 0; mt < 2; mt++) {
                ldsm4(ah[mt], sb + M1_AH + a_off + mt * 1280 + ks * 32);
                ldsm4(al[mt], sb + M1_AL + a_off + mt * 1280 + ks * 32);
            }
            uint32_t fh[2][4], fl[2][4], gh[2][4], gl[2][4];
            #pragma unroll
            for (int q = 0; q < 2; q++) {
                uint32_t bo = bt_off + ks * 2304 + q * 32;   // 16 k-rows * 144B = 2304
                ldsm4t(fh[q], sb + M1_FH + bo);
                ldsm4t(fl[q], sb + M1_FL + bo);
                ldsm4t(gh[q], sb + M1_GH + bo);
                ldsm4t(gl[q], sb + M1_GL + bo);
            }
            #pragma unroll
            for (int mt = 0; mt < 2; mt++)
                #pragma unroll
                for (int nt = 0; nt < 4; nt++) {
                    const uint32_t* FH = &fh[nt >> 1][(nt & 1) * 2];
                    const uint32_t* FL = &fl[nt >> 1][(nt & 1) * 2];
                    const uint32_t* GH = &gh[nt >> 1][(nt & 1) * 2];
                    const uint32_t* GL = &gl[nt >> 1][(nt & 1) * 2];
                    mma_bf16(acch[mt][nt], ah[mt], FH);
                    mma_bf16(acch[mt][nt], al[mt], FH);
                    mma_bf16(acch[mt][nt], ah[mt], FL);
                    mma_bf16(accg[mt][nt], ah[mt], GH);
                    mma_bf16(accg[mt][nt], al[mt], GH);
                    mma_bf16(accg[mt][nt], ah[mt], GL);
                }
        }
    }

    // epilogue: silu(h*g) -> fp32 g_act
    const int qr = lane >> 2, qc = (lane & 3) * 2;
    #pragma unroll
    for (int mt = 0; mt < 2; mt++) {
        #pragma unroll
        for (int nt = 0; nt < 4; nt++) {
            const int col = n0 + nwarp * 32 + nt * 8 + qc;
            const float b0 = bfc[e * NH + col], b1 = bfc[e * NH + col + 1];
            const float c0 = bgt[e * NH + col], c1 = bgt[e * NH + col + 1];
            #pragma unroll
            for (int hf = 0; hf < 2; hf++) {
                const int row = m0 + mwarp * 32 + mt * 16 + qr + hf * 8;
                float h0 = acch[mt][nt][hf * 2 + 0] + b0;
                float h1 = acch[mt][nt][hf * 2 + 1] + b1;
                float g0 = accg[mt][nt][hf * 2 + 0] + c0;
                float g1 = accg[mt][nt][hf * 2 + 1] + c1;
                float z0 = h0 * g0, z1 = h1 * g1;
                float2 o;
                o.x = z0 / (1.f + expf(-z0));
                o.y = z1 / (1.f + expf(-z1));
                *(float2*)(g_act + ((size_t)(e * NM + row)) * NH + col) = o;
            }
        }
    }
}

// ---------------------------------------------------------------- mlp2 (HMMA, hi/lo compensated)
// A regions: A_H @0, A_L @10240 ; B regions: B_H @20480, B_L @25088 ; total 29696 B
#define M2_AH 0
#define M2_AL 10240
#define M2_BH 20480
#define M2_BL 25088

__global__ void __launch_bounds__(256) mlp2_kernel(const float* __restrict__ wp,
                                                   const float* __restrict__ bp) {
    __shared__ __align__(16) unsigned char SM[29696];
    const uint32_t sb = smem_u32(SM);
    const int tid = threadIdx.x;
    const int e = blockIdx.z;
    const int n0 = blockIdx.x * 64, m0 = blockIdx.y * 128;

    const float* A  = g_act + ((size_t)e * NM + m0) * NH;   // [M][K] fp32
    const float* W  = wp + (size_t)e * NH * NC;             // [K=3072][N=768]

    const int wid = tid >> 5, lane = tid & 31;
    const int mwarp = wid >> 1, nwarp = wid & 1;
    const uint32_t a_off = (uint32_t)(mwarp * 32 + (lane & 15)) * 80 + ((lane & 16) ? 16 : 0);
    const uint32_t bt_off = (uint32_t)(lane & 15) * 144 + ((lane & 16) ? 16 : 0) + nwarp * 64;

    float acc[2][4][4] = {};

    const int NS = NH / 32;   // 96
    for (int s = 0; s < NS; s++) {
        const int k0 = s * 32;
        __syncthreads();
        #pragma unroll
        for (int i = 0; i < 4; i++) {
            int j = tid + i * 256;
            int r = j >> 3, ch = j & 7;
            float4 v = *(const float4*)(A + (size_t)r * NH + k0 + ch * 4);
            uint2 h, l;
            split4(v, h, l);
            uint32_t d = (uint32_t)r * 80 + ch * 8;
            *(uint2*)(SM + M2_AH + d) = h;
            *(uint2*)(SM + M2_AL + d) = l;
        }
        #pragma unroll
        for (int i = 0; i < 2; i++) {
            int j = tid + i * 256;
            int r = j >> 4, ch = j & 15;
            float4 v = *(const float4*)(W + (size_t)(k0 + r) * NC + n0 + ch * 4);
            uint2 h, l;
            split4(v, h, l);
            uint32_t d = (uint32_t)r * 144 + ch * 8;
            *(uint2*)(SM + M2_BH + d) = h;
            *(uint2*)(SM + M2_BL + d) = l;
        }
        __syncthreads();

        #pragma unroll
        for (int ks = 0; ks < 2; ks++) {
            uint32_t ah[2][4], al[2][4];
            #pragma unroll
            for (int mt = 0; mt < 2; mt++) {
                ldsm4(ah[mt], sb + M2_AH + a_off + mt * 1280 + ks * 32);
                ldsm4(al[mt], sb + M2_AL + a_off + mt * 1280 + ks * 32);
            }
            uint32_t bh[2][4], bl[2][4];
            #pragma unroll
            for (int q = 0; q < 2; q++) {
                uint32_t bo = bt_off + ks * 2304 + q * 32;
                ldsm4t(bh[q], sb + M2_BH + bo);
                ldsm4t(bl[q], sb + M2_BL + bo);
            }
            #pragma unroll
            for (int mt = 0; mt < 2; mt++)
                #pragma unroll
                for (int nt = 0; nt < 4; nt++) {
                    const uint32_t* BH = &bh[nt >> 1][(nt & 1) * 2];
                    const uint32_t* BL = &bl[nt >> 1][(nt & 1) * 2];
                    mma_bf16(acc[mt][nt], ah[mt], BH);
                    mma_bf16(acc[mt][nt], al[mt], BH);
                    mma_bf16(acc[mt][nt], ah[mt], BL);
                }
        }
    }

    const int qr = lane >> 2, qc = (lane & 3) * 2;
    #pragma unroll
    for (int mt = 0; mt < 2; mt++) {
        #pragma unroll
        for (int nt = 0; nt < 4; nt++) {
            const int col = n0 + nwarp * 32 + nt * 8 + qc;
            const float b0 = bp[e * NC + col], b1 = bp[e * NC + col + 1];
            #pragma unroll
            for (int hf = 0; hf < 2; hf++) {
                const int row = m0 + mwarp * 32 + mt * 16 + qr + hf * 8;
                float2 o;
                o.x = acc[mt][nt][hf * 2 + 0] + b0;
                o.y = acc[mt][nt][hf * 2 + 1] + b1;
                *(float2*)(g_o + ((size_t)(e * NM + row)) * NC + col) = o;
            }
        }
    }
}

// ---------------------------------------------------------------- combine (unchanged, passing)
__global__ void combine_kernel(float* __restrict__ out) {
    int token = blockIdx.x;
    int b = token / NT;

    int e0 = g_ei[token * 2 + 0], e1 = g_ei[token * 2 + 1];
    float p0 = g_p[token * 2 + 0], p1 = g_p[token * 2 + 1];
    int q0 = min(g_pos[token * 2 + 0], NCAP - 1);
    int q1 = min(g_pos[token * 2 + 1], NCAP - 1);

    const float4* r0 = (const float4*)(g_o + ((size_t)e0 * NM + b * NCAP + q0) * NC);
    const float4* r1 = (const float4*)(g_o + ((size_t)e1 * NM + b * NCAP + q1) * NC);

    int c = threadIdx.x;
    float4 v0 = r0[c], v1 = r1[c];
    float4 o;
    o.x = p0 * v0.x + p1 * v1.x;
    o.y = p0 * v0.y + p1 * v1.y;
    o.z = p0 * v0.z + p1 * v1.z;
    o.w = p0 * v0.w + p1 * v1.w;
    ((float4*)out)[(size_t)token * (NC / 4) + c] = o;
}

// ---------------------------------------------------------------- launch
extern "C" void kernel_launch(void* const* d_in, const int* in_sizes, int n_in,
                              void* d_out, int out_size) {
    const float* x        = (const float*)d_in[0];
    const float* w_router = (const float*)d_in[1];
    const float* b_router = (const float*)d_in[2];
    const float* w_c_fc   = (const float*)d_in[3];
    const float* b_c_fc   = (const float*)d_in[4];
    const float* w_gate   = (const float*)d_in[5];
    const float* b_gate   = (const float*)d_in[6];
    const float* w_c_proj = (const float*)d_in[7];
    const float* b_c_proj = (const float*)d_in[8];
    float* out = (float*)d_out;

    router_kernel<<<NB * NT / 8, 256>>>(x, w_router, b_router);
    fill_src_kernel<<<(NE * NM + 255) / 256, 256>>>();
    pos_kernel<<<1, 256>>>();

    mlp1_kernel<<<dim3(NH / 64, NM / 128, NE), 256>>>(x, w_c_fc, b_c_fc, w_gate, b_gate);
    mlp2_kernel<<<dim3(NC / 64, NM / 128, NE), 256>>>(w_c_proj, b_c_proj);

    combine_kernel<<<NB * NT, 192>>>(out);
}

// round 6
// speedup vs baseline: 2.0510x; 1.0509x over previous
#include <cuda_runtime.h>
#include <cuda_bf16.h>
#include <math.h>
#include <stdint.h>

// ---------------------------------------------------------------- dims
#define NB   8
#define NT   2048
#define NC   768
#define NE   8
#define NKT  2
#define NH   3072
#define NCAP 640
#define NM   (NB * NCAP)   // 5120 rows per expert

// ---------------------------------------------------------------- helpers
__device__ __forceinline__ uint32_t smem_u32(const void* p) {
    uint32_t a;
    asm("{ .reg .u64 t; cvta.to.shared.u64 t, %1; cvt.u32.u64 %0, t; }"
        : "=r"(a) : "l"(p));
    return a;
}
__device__ __forceinline__ void ldsm4(uint32_t* r, uint32_t a) {
    asm volatile("ldmatrix.sync.aligned.m8n8.x4.shared.b16 {%0,%1,%2,%3}, [%4];"
        : "=r"(r[0]), "=r"(r[1]), "=r"(r[2]), "=r"(r[3]) : "r"(a));
}
__device__ __forceinline__ void ldsm4t(uint32_t* r, uint32_t a) {
    asm volatile("ldmatrix.sync.aligned.m8n8.x4.trans.shared.b16 {%0,%1,%2,%3}, [%4];"
        : "=r"(r[0]), "=r"(r[1]), "=r"(r[2]), "=r"(r[3]) : "r"(a));
}
__device__ __forceinline__ void mma_bf16(float* d, const uint32_t* a, const uint32_t* b) {
    asm volatile(
        "mma.sync.aligned.m16n8k16.row.col.f32.bf16.bf16.f32 "
        "{%0,%1,%2,%3}, {%4,%5,%6,%7}, {%8,%9}, {%0,%1,%2,%3};"
        : "+f"(d[0]), "+f"(d[1]), "+f"(d[2]), "+f"(d[3])
        : "r"(a[0]), "r"(a[1]), "r"(a[2]), "r"(a[3]), "r"(b[0]), "r"(b[1]));
}
// split float4 into packed bf16 hi (uint2) and lo residual (uint2)
__device__ __forceinline__ void split4(float4 v, uint2& h, uint2& l) {
    __nv_bfloat16 h0 = __float2bfloat16(v.x), h1 = __float2bfloat16(v.y);
    __nv_bfloat16 h2 = __float2bfloat16(v.z), h3 = __float2bfloat16(v.w);
    float r0 = v.x - __bfloat162float(h0), r1 = v.y - __bfloat162float(h1);
    float r2 = v.z - __bfloat162float(h2), r3 = v.w - __bfloat162float(h3);
    h.x = (uint32_t)__bfloat16_as_ushort(h0) | ((uint32_t)__bfloat16_as_ushort(h1) << 16);
    h.y = (uint32_t)__bfloat16_as_ushort(h2) | ((uint32_t)__bfloat16_as_ushort(h3) << 16);
    l.x = (uint32_t)__bfloat16_as_ushort(__float2bfloat16(r0))
        | ((uint32_t)__bfloat16_as_ushort(__float2bfloat16(r1)) << 16);
    l.y = (uint32_t)__bfloat16_as_ushort(__float2bfloat16(r2))
        | ((uint32_t)__bfloat16_as_ushort(__float2bfloat16(r3)) << 16);
}

// ---------------------------------------------------------------- scratch
__device__ __nv_bfloat16 g_acth[(size_t)NE * NM * NH];  // activation hi
__device__ __nv_bfloat16 g_actl[(size_t)NE * NM * NH];  // activation lo
__device__ float g_o  [(size_t)NE * NM * NC];
__device__ float g_p  [NB * NT * NKT];
__device__ int   g_ei [NB * NT * NKT];
__device__ int   g_pos[NB * NT * NKT];
__device__ int   g_src[NE * NM];

// ---------------------------------------------------------------- router (unchanged, passing)
__global__ void router_kernel(const float* __restrict__ x,
                              const float* __restrict__ wr,
                              const float* __restrict__ br) {
    __shared__ float ws[NC * NE];
    int tid = threadIdx.x;
    const float4* wr4 = (const float4*)wr;
    float4* ws4 = (float4*)ws;
    #pragma unroll
    for (int i = tid; i < NC * NE / 4; i += 256) ws4[i] = wr4[i];
    __syncthreads();

    int warp = tid >> 5, lane = tid & 31;
    int token = blockIdx.x * 8 + warp;
    const float* xrow = x + (size_t)token * NC;

    float acc[NE];
    #pragma unroll
    for (int e = 0; e < NE; e++) acc[e] = 0.f;
    for (int c = lane; c < NC; c += 32) {
        float xv = xrow[c];
        #pragma unroll
        for (int e = 0; e < NE; e++) acc[e] = fmaf(xv, ws[c * NE + e], acc[e]);
    }
    #pragma unroll
    for (int e = 0; e < NE; e++) {
        #pragma unroll
        for (int off = 16; off; off >>= 1)
            acc[e] += __shfl_xor_sync(0xffffffffu, acc[e], off);
    }
    if (lane == 0) {
        float l[NE], p[NE];
        float mx = -1e30f;
        #pragma unroll
        for (int e = 0; e < NE; e++) { l[e] = acc[e] + br[e]; mx = fmaxf(mx, l[e]); }
        float s = 0.f;
        #pragma unroll
        for (int e = 0; e < NE; e++) { p[e] = expf(l[e] - mx); s += p[e]; }
        float inv = 1.f / s;
        #pragma unroll
        for (int e = 0; e < NE; e++) p[e] *= inv;

        int i1 = 0; float p1 = p[0];
        #pragma unroll
        for (int e = 1; e < NE; e++) if (p[e] > p1) { p1 = p[e]; i1 = e; }
        int i2 = -1; float p2 = -1.f;
        #pragma unroll
        for (int e = 0; e < NE; e++) if (e != i1 && p[e] > p2) { p2 = p[e]; i2 = e; }

        g_p [token * 2 + 0] = p1;  g_p [token * 2 + 1] = p2;
        g_ei[token * 2 + 0] = i1;  g_ei[token * 2 + 1] = i2;
    }
}

__global__ void fill_src_kernel() {
    int i = blockIdx.x * 256 + threadIdx.x;
    if (i < NE * NM) g_src[i] = -1;
}

// capacity scan, exact k-major cumsum order per batch (unchanged, passing)
__global__ void pos_kernel() {
    __shared__ int cnt[8][NE];
    int w = threadIdx.x >> 5, lane = threadIdx.x & 31;
    int b = w;
    if (lane < NE) cnt[w][lane] = 0;
    __syncwarp();
    for (int k = 0; k < NKT; k++) {
        for (int t0 = 0; t0 < NT; t0 += 32) {
            int t = t0 + lane;
            int e = g_ei[(b * NT + t) * NKT + k];
            unsigned mask = __match_any_sync(0xffffffffu, e);
            int prefix = __popc(mask & ((1u << lane) - 1u));
            int base = cnt[w][e];
            __syncwarp();
            int pos = base + prefix;
            g_pos[(b * NT + t) * NKT + k] = pos;
            if (pos < NCAP) g_src[e * NM + b * NCAP + pos] = b * NT + t;
            if (lane == (31 - __clz(mask))) cnt[w][e] = base + __popc(mask);
            __syncwarp();
        }
    }
}

// ---------------------------------------------------------------- mlp1 (HMMA hi/lo, reg-prefetch)
#define M1_AH 0
#define M1_AL 10240
#define M1_FH 20480
#define M1_FL 25088
#define M1_GH 29696
#define M1_GL 34304

__global__ void __launch_bounds__(256) mlp1_kernel(const float* __restrict__ x,
                                                   const float* __restrict__ wfc,
                                                   const float* __restrict__ bfc,
                                                   const float* __restrict__ wgt,
                                                   const float* __restrict__ bgt) {
    __shared__ __align__(16) unsigned char SM[38912];
    __shared__ int s_src[128];
    const uint32_t sb = smem_u32(SM);
    const int tid = threadIdx.x;
    const int e = blockIdx.z;
    const int n0 = blockIdx.x * 64, m0 = blockIdx.y * 128;

    if (tid < 128) s_src[tid] = g_src[e * NM + m0 + tid];
    __syncthreads();

    const float* Wf = wfc + (size_t)e * NC * NH;   // [K=768][N=3072]
    const float* Wg = wgt + (size_t)e * NC * NH;

    const int wid = tid >> 5, lane = tid & 31;
    const int mwarp = wid >> 1, nwarp = wid & 1;
    const uint32_t a_off = (uint32_t)(mwarp * 32 + (lane & 15)) * 80 + ((lane & 16) ? 16 : 0);
    const uint32_t bt_off = (uint32_t)(lane & 15) * 144 + ((lane & 16) ? 16 : 0) + nwarp * 64;

    float acch[2][4][4] = {};
    float accg[2][4][4] = {};

    // prefetch registers
    float4 pA[4], pF[2], pG[2];

    auto ld_stage = [&](int s) {
        const int k0 = s * 32;
        #pragma unroll
        for (int i = 0; i < 4; i++) {
            int j = tid + i * 256;
            int r = j >> 3, ch = j & 7;
            int srow = s_src[r];
            pA[i] = (srow >= 0)
                ? *(const float4*)(x + (size_t)srow * NC + k0 + ch * 4)
                : make_float4(0.f, 0.f, 0.f, 0.f);
        }
        #pragma unroll
        for (int i = 0; i < 2; i++) {
            int j = tid + i * 256;
            int r = j >> 4, ch = j & 15;
            size_t goff = (size_t)(k0 + r) * NH + n0 + ch * 4;
            pF[i] = *(const float4*)(Wf + goff);
            pG[i] = *(const float4*)(Wg + goff);
        }
    };
    auto st_stage = [&]() {
        #pragma unroll
        for (int i = 0; i < 4; i++) {
            int j = tid + i * 256;
            int r = j >> 3, ch = j & 7;
            uint2 h, l;
            split4(pA[i], h, l);
            uint32_t d = (uint32_t)r * 80 + ch * 8;
            *(uint2*)(SM + M1_AH + d) = h;
            *(uint2*)(SM + M1_AL + d) = l;
        }
        #pragma unroll
        for (int i = 0; i < 2; i++) {
            int j = tid + i * 256;
            int r = j >> 4, ch = j & 15;
            uint2 fh, fl, gh, gl;
            split4(pF[i], fh, fl);
            split4(pG[i], gh, gl);
            uint32_t d = (uint32_t)r * 144 + ch * 8;
            *(uint2*)(SM + M1_FH + d) = fh;
            *(uint2*)(SM + M1_FL + d) = fl;
            *(uint2*)(SM + M1_GH + d) = gh;
            *(uint2*)(SM + M1_GL + d) = gl;
        }
    };

    const int NS = NC / 32;   // 24
    ld_stage(0);
    for (int s = 0; s < NS; s++) {
        __syncthreads();
        st_stage();
        __syncthreads();
        if (s + 1 < NS) ld_stage(s + 1);   // overlaps with compute below

        #pragma unroll
        for (int ks = 0; ks < 2; ks++) {
            uint32_t ah[2][4], al[2][4];
            #pragma unroll
            for (int mt = 0; mt < 2; mt++) {
                ldsm4(ah[mt], sb + M1_AH + a_off + mt * 1280 + ks * 32);
                ldsm4(al[mt], sb + M1_AL + a_off + mt * 1280 + ks * 32);
            }
            uint32_t fh[2][4], fl[2][4], gh[2][4], gl[2][4];
            #pragma unroll
            for (int q = 0; q < 2; q++) {
                uint32_t bo = bt_off + ks * 2304 + q * 32;
                ldsm4t(fh[q], sb + M1_FH + bo);
                ldsm4t(fl[q], sb + M1_FL + bo);
                ldsm4t(gh[q], sb + M1_GH + bo);
                ldsm4t(gl[q], sb + M1_GL + bo);
            }
            #pragma unroll
            for (int mt = 0; mt < 2; mt++)
                #pragma unroll
                for (int nt = 0; nt < 4; nt++) {
                    const uint32_t* FH = &fh[nt >> 1][(nt & 1) * 2];
                    const uint32_t* FL = &fl[nt >> 1][(nt & 1) * 2];
                    const uint32_t* GH = &gh[nt >> 1][(nt & 1) * 2];
                    const uint32_t* GL = &gl[nt >> 1][(nt & 1) * 2];
                    mma_bf16(acch[mt][nt], ah[mt], FH);
                    mma_bf16(acch[mt][nt], al[mt], FH);
                    mma_bf16(acch[mt][nt], ah[mt], FL);
                    mma_bf16(accg[mt][nt], ah[mt], GH);
                    mma_bf16(accg[mt][nt], al[mt], GH);
                    mma_bf16(accg[mt][nt], ah[mt], GL);
                }
        }
    }

    // epilogue: silu(h*g) -> bf16 hi/lo activations
    const int qr = lane >> 2, qc = (lane & 3) * 2;
    #pragma unroll
    for (int mt = 0; mt < 2; mt++) {
        #pragma unroll
        for (int nt = 0; nt < 4; nt++) {
            const int col = n0 + nwarp * 32 + nt * 8 + qc;
            const float b0 = bfc[e * NH + col], b1 = bfc[e * NH + col + 1];
            const float c0 = bgt[e * NH + col], c1 = bgt[e * NH + col + 1];
            #pragma unroll
            for (int hf = 0; hf < 2; hf++) {
                const int row = m0 + mwarp * 32 + mt * 16 + qr + hf * 8;
                float h0 = acch[mt][nt][hf * 2 + 0] + b0;
                float h1 = acch[mt][nt][hf * 2 + 1] + b1;
                float g0 = accg[mt][nt][hf * 2 + 0] + c0;
                float g1 = accg[mt][nt][hf * 2 + 1] + c1;
                float z0 = h0 * g0, z1 = h1 * g1;
                float v0 = z0 / (1.f + expf(-z0));
                float v1 = z1 / (1.f + expf(-z1));
                __nv_bfloat16 H0 = __float2bfloat16(v0), H1 = __float2bfloat16(v1);
                float r0 = v0 - __bfloat162float(H0);
                float r1 = v1 - __bfloat162float(H1);
                uint32_t hi = (uint32_t)__bfloat16_as_ushort(H0)
                            | ((uint32_t)__bfloat16_as_ushort(H1) << 16);
                uint32_t lo = (uint32_t)__bfloat16_as_ushort(__float2bfloat16(r0))
                            | ((uint32_t)__bfloat16_as_ushort(__float2bfloat16(r1)) << 16);
                size_t off = ((size_t)(e * NM + row)) * NH + col;
                *(uint32_t*)(g_acth + off) = hi;
                *(uint32_t*)(g_actl + off) = lo;
            }
        }
    }
}

// ---------------------------------------------------------------- mlp2 (HMMA hi/lo, reg-prefetch)
#define M2_AH 0
#define M2_AL 10240
#define M2_BH 20480
#define M2_BL 25088

__global__ void __launch_bounds__(256) mlp2_kernel(const float* __restrict__ wp,
                                                   const float* __restrict__ bp) {
    __shared__ __align__(16) unsigned char SM[29696];
    const uint32_t sb = smem_u32(SM);
    const int tid = threadIdx.x;
    const int e = blockIdx.z;
    const int n0 = blockIdx.x * 64, m0 = blockIdx.y * 128;

    const __nv_bfloat16* Ah = g_acth + ((size_t)e * NM + m0) * NH;
    const __nv_bfloat16* Al = g_actl + ((size_t)e * NM + m0) * NH;
    const float* W = wp + (size_t)e * NH * NC;   // [K=3072][N=768]

    const int wid = tid >> 5, lane = tid & 31;
    const int mwarp = wid >> 1, nwarp = wid & 1;
    const uint32_t a_off = (uint32_t)(mwarp * 32 + (lane & 15)) * 80 + ((lane & 16) ? 16 : 0);
    const uint32_t bt_off = (uint32_t)(lane & 15) * 144 + ((lane & 16) ? 16 : 0) + nwarp * 64;

    float acc[2][4][4] = {};

    uint2 pAh[4], pAl[4];
    float4 pB[2];

    auto ld_stage = [&](int s) {
        const int k0 = s * 32;
        #pragma unroll
        for (int i = 0; i < 4; i++) {
            int j = tid + i * 256;
            int r = j >> 3, ch = j & 7;
            size_t goff = (size_t)r * NH + k0 + ch * 4;
            pAh[i] = *(const uint2*)(Ah + goff);
            pAl[i] = *(const uint2*)(Al + goff);
        }
        #pragma unroll
        for (int i = 0; i < 2; i++) {
            int j = tid + i * 256;
            int r = j >> 4, ch = j & 15;
            pB[i] = *(const float4*)(W + (size_t)(k0 + r) * NC + n0 + ch * 4);
        }
    };
    auto st_stage = [&]() {
        #pragma unroll
        for (int i = 0; i < 4; i++) {
            int j = tid + i * 256;
            int r = j >> 3, ch = j & 7;
            uint32_t d = (uint32_t)r * 80 + ch * 8;
            *(uint2*)(SM + M2_AH + d) = pAh[i];
            *(uint2*)(SM + M2_AL + d) = pAl[i];
        }
        #pragma unroll
        for (int i = 0; i < 2; i++) {
            int j = tid + i * 256;
            int r = j >> 4, ch = j & 15;
            uint2 h, l;
            split4(pB[i], h, l);
            uint32_t d = (uint32_t)r * 144 + ch * 8;
            *(uint2*)(SM + M2_BH + d) = h;
            *(uint2*)(SM + M2_BL + d) = l;
        }
    };

    const int NS = NH / 32;   // 96
    ld_stage(0);
    for (int s = 0; s < NS; s++) {
        __syncthreads();
        st_stage();
        __syncthreads();
        if (s + 1 < NS) ld_stage(s + 1);

        #pragma unroll
        for (int ks = 0; ks < 2; ks++) {
            uint32_t ah[2][4], al[2][4];
            #pragma unroll
            for (int mt = 0; mt < 2; mt++) {
                ldsm4(ah[mt], sb + M2_AH + a_off + mt * 1280 + ks * 32);
                ldsm4(al[mt], sb + M2_AL + a_off + mt * 1280 + ks * 32);
            }
            uint32_t bh[2][4], bl[2][4];
            #pragma unroll
            for (int q = 0; q < 2; q++) {
                uint32_t bo = bt_off + ks * 2304 + q * 32;
                ldsm4t(bh[q], sb + M2_BH + bo);
                ldsm4t(bl[q], sb + M2_BL + bo);
            }
            #pragma unroll
            for (int mt = 0; mt < 2; mt++)
                #pragma unroll
                for (int nt = 0; nt < 4; nt++) {
                    const uint32_t* BH = &bh[nt >> 1][(nt & 1) * 2];
                    const uint32_t* BL = &bl[nt >> 1][(nt & 1) * 2];
                    mma_bf16(acc[mt][nt], ah[mt], BH);
                    mma_bf16(acc[mt][nt], al[mt], BH);
                    mma_bf16(acc[mt][nt], ah[mt], BL);
                }
        }
    }

    const int qr = lane >> 2, qc = (lane & 3) * 2;
    #pragma unroll
    for (int mt = 0; mt < 2; mt++) {
        #pragma unroll
        for (int nt = 0; nt < 4; nt++) {
            const int col = n0 + nwarp * 32 + nt * 8 + qc;
            const float b0 = bp[e * NC + col], b1 = bp[e * NC + col + 1];
            #pragma unroll
            for (int hf = 0; hf < 2; hf++) {
                const int row = m0 + mwarp * 32 + mt * 16 + qr + hf * 8;
                float2 o;
                o.x = acc[mt][nt][hf * 2 + 0] + b0;
                o.y = acc[mt][nt][hf * 2 + 1] + b1;
                *(float2*)(g_o + ((size_t)(e * NM + row)) * NC + col) = o;
            }
        }
    }
}

// ---------------------------------------------------------------- combine (unchanged, passing)
__global__ void combine_kernel(float* __restrict__ out) {
    int token = blockIdx.x;
    int b = token / NT;

    int e0 = g_ei[token * 2 + 0], e1 = g_ei[token * 2 + 1];
    float p0 = g_p[token * 2 + 0], p1 = g_p[token * 2 + 1];
    int q0 = min(g_pos[token * 2 + 0], NCAP - 1);
    int q1 = min(g_pos[token * 2 + 1], NCAP - 1);

    const float4* r0 = (const float4*)(g_o + ((size_t)e0 * NM + b * NCAP + q0) * NC);
    const float4* r1 = (const float4*)(g_o + ((size_t)e1 * NM + b * NCAP + q1) * NC);

    int c = threadIdx.x;
    float4 v0 = r0[c], v1 = r1[c];
    float4 o;
    o.x = p0 * v0.x + p1 * v1.x;
    o.y = p0 * v0.y + p1 * v1.y;
    o.z = p0 * v0.z + p1 * v1.z;
    o.w = p0 * v0.w + p1 * v1.w;
    ((float4*)out)[(size_t)token * (NC / 4) + c] = o;
}

// ---------------------------------------------------------------- launch
extern "C" void kernel_launch(void* const* d_in, const int* in_sizes, int n_in,
                              void* d_out, int out_size) {
    const float* x        = (const float*)d_in[0];
    const float* w_router = (const float*)d_in[1];
    const float* b_router = (const float*)d_in[2];
    const float* w_c_fc   = (const float*)d_in[3];
    const float* b_c_fc   = (const float*)d_in[4];
    const float* w_gate   = (const float*)d_in[5];
    const float* b_gate   = (const float*)d_in[6];
    const float* w_c_proj = (const float*)d_in[7];
    const float* b_c_proj = (const float*)d_in[8];
    float* out = (float*)d_out;

    router_kernel<<<NB * NT / 8, 256>>>(x, w_router, b_router);
    fill_src_kernel<<<(NE * NM + 255) / 256, 256>>>();
    pos_kernel<<<1, 256>>>();

    mlp1_kernel<<<dim3(NH / 64, NM / 128, NE), 256>>>(x, w_c_fc, b_c_fc, w_gate, b_gate);
    mlp2_kernel<<<dim3(NC / 64, NM / 128, NE), 256>>>(w_c_proj, b_c_proj);

    combine_kernel<<<NB * NT, 192>>>(out);
}

// round 8
// speedup vs baseline: 2.4664x; 1.2025x over previous
#include <cuda_runtime.h>
#include <cuda_bf16.h>
#include <math.h>
#include <stdint.h>

// ---------------------------------------------------------------- dims
#define NB   8
#define NT   2048
#define NC   768
#define NE   8
#define NKT  2
#define NH   3072
#define NCAP 640
#define NM   (NB * NCAP)   // 5120 rows per expert
#define WSZ  ((size_t)NE * NC * NH)   // elements per weight tensor

// ---------------------------------------------------------------- helpers
__device__ __forceinline__ uint32_t smem_u32(const void* p) {
    uint32_t a;
    asm("{ .reg .u64 t; cvta.to.shared.u64 t, %1; cvt.u32.u64 %0, t; }"
        : "=r"(a) : "l"(p));
    return a;
}
__device__ __forceinline__ void ldsm4(uint32_t* r, uint32_t a) {
    asm volatile("ldmatrix.sync.aligned.m8n8.x4.shared.b16 {%0,%1,%2,%3}, [%4];"
        : "=r"(r[0]), "=r"(r[1]), "=r"(r[2]), "=r"(r[3]) : "r"(a));
}
__device__ __forceinline__ void ldsm4t(uint32_t* r, uint32_t a) {
    asm volatile("ldmatrix.sync.aligned.m8n8.x4.trans.shared.b16 {%0,%1,%2,%3}, [%4];"
        : "=r"(r[0]), "=r"(r[1]), "=r"(r[2]), "=r"(r[3]) : "r"(a));
}
__device__ __forceinline__ void mma_bf16(float* d, const uint32_t* a, const uint32_t* b) {
    asm volatile(
        "mma.sync.aligned.m16n8k16.row.col.f32.bf16.bf16.f32 "
        "{%0,%1,%2,%3}, {%4,%5,%6,%7}, {%8,%9}, {%0,%1,%2,%3};"
        : "+f"(d[0]), "+f"(d[1]), "+f"(d[2]), "+f"(d[3])
        : "r"(a[0]), "r"(a[1]), "r"(a[2]), "r"(a[3]), "r"(b[0]), "r"(b[1]));
}
// split float4 into packed bf16 hi (uint2) and lo residual (uint2)
__device__ __forceinline__ void split4(float4 v, uint2& h, uint2& l) {
    __nv_bfloat16 h0 = __float2bfloat16(v.x), h1 = __float2bfloat16(v.y);
    __nv_bfloat16 h2 = __float2bfloat16(v.z), h3 = __float2bfloat16(v.w);
    float r0 = v.x - __bfloat162float(h0), r1 = v.y - __bfloat162float(h1);
    float r2 = v.z - __bfloat162float(h2), r3 = v.w - __bfloat162float(h3);
    h.x = (uint32_t)__bfloat16_as_ushort(h0) | ((uint32_t)__bfloat16_as_ushort(h1) << 16);
    h.y = (uint32_t)__bfloat16_as_ushort(h2) | ((uint32_t)__bfloat16_as_ushort(h3) << 16);
    l.x = (uint32_t)__bfloat16_as_ushort(__float2bfloat16(r0))
        | ((uint32_t)__bfloat16_as_ushort(__float2bfloat16(r1)) << 16);
    l.y = (uint32_t)__bfloat16_as_ushort(__float2bfloat16(r2))
        | ((uint32_t)__bfloat16_as_ushort(__float2bfloat16(r3)) << 16);
}

// ---------------------------------------------------------------- scratch (≈654MB total)
__device__ __nv_bfloat16 g_acth[(size_t)NE * NM * NH];  // activation hi (252MB)
__device__ __nv_bfloat16 g_actl[(size_t)NE * NM * NH];  // activation lo (252MB)
// union buffer (151MB): phase 1 = fc/gate weight splits (wsplit + mlp1),
// phase 2 = g_o fp32 expert outputs (mlp2 + combine). mlp1 completes before
// mlp2 launches (same stream), so the reuse is race-free.
__device__ __align__(1024) unsigned char g_u[4 * WSZ * 2];
__device__ float g_p  [NB * NT * NKT];
__device__ int   g_ei [NB * NT * NKT];
__device__ int   g_pos[NB * NT * NKT];
__device__ int   g_src[NE * NM];

// ---------------------------------------------------------------- prep: elementwise hi/lo split
__global__ void wsplit_kernel(const float* __restrict__ in,
                              __nv_bfloat16* __restrict__ oh,
                              __nv_bfloat16* __restrict__ ol) {
    size_t i = (size_t)blockIdx.x * 256 + threadIdx.x;   // float4 index
    float4 v = ((const float4*)in)[i];
    uint2 h, l;
    split4(v, h, l);
    ((uint2*)oh)[i] = h;
    ((uint2*)ol)[i] = l;
}

// ---------------------------------------------------------------- router (unchanged, passing)
__global__ void router_kernel(const float* __restrict__ x,
                              const float* __restrict__ wr,
                              const float* __restrict__ br) {
    __shared__ float ws[NC * NE];
    int tid = threadIdx.x;
    const float4* wr4 = (const float4*)wr;
    float4* ws4 = (float4*)ws;
    #pragma unroll
    for (int i = tid; i < NC * NE / 4; i += 256) ws4[i] = wr4[i];
    __syncthreads();

    int warp = tid >> 5, lane = tid & 31;
    int token = blockIdx.x * 8 + warp;
    const float* xrow = x + (size_t)token * NC;

    float acc[NE];
    #pragma unroll
    for (int e = 0; e < NE; e++) acc[e] = 0.f;
    for (int c = lane; c < NC; c += 32) {
        float xv = xrow[c];
        #pragma unroll
        for (int e = 0; e < NE; e++) acc[e] = fmaf(xv, ws[c * NE + e], acc[e]);
    }
    #pragma unroll
    for (int e = 0; e < NE; e++) {
        #pragma unroll
        for (int off = 16; off; off >>= 1)
            acc[e] += __shfl_xor_sync(0xffffffffu, acc[e], off);
    }
    if (lane == 0) {
        float l[NE], p[NE];
        float mx = -1e30f;
        #pragma unroll
        for (int e = 0; e < NE; e++) { l[e] = acc[e] + br[e]; mx = fmaxf(mx, l[e]); }
        float s = 0.f;
        #pragma unroll
        for (int e = 0; e < NE; e++) { p[e] = expf(l[e] - mx); s += p[e]; }
        float inv = 1.f / s;
        #pragma unroll
        for (int e = 0; e < NE; e++) p[e] *= inv;

        int i1 = 0; float p1 = p[0];
        #pragma unroll
        for (int e = 1; e < NE; e++) if (p[e] > p1) { p1 = p[e]; i1 = e; }
        int i2 = -1; float p2 = -1.f;
        #pragma unroll
        for (int e = 0; e < NE; e++) if (e != i1 && p[e] > p2) { p2 = p[e]; i2 = e; }

        g_p [token * 2 + 0] = p1;  g_p [token * 2 + 1] = p2;
        g_ei[token * 2 + 0] = i1;  g_ei[token * 2 + 1] = i2;
    }
}

__global__ void fill_src_kernel() {
    int i = blockIdx.x * 256 + threadIdx.x;
    if (i < NE * NM) g_src[i] = -1;
}

// capacity scan, exact k-major cumsum order per batch (unchanged, passing)
__global__ void pos_kernel() {
    __shared__ int cnt[8][NE];
    int w = threadIdx.x >> 5, lane = threadIdx.x & 31;
    int b = w;
    if (lane < NE) cnt[w][lane] = 0;
    __syncwarp();
    for (int k = 0; k < NKT; k++) {
        for (int t0 = 0; t0 < NT; t0 += 32) {
            int t = t0 + lane;
            int e = g_ei[(b * NT + t) * NKT + k];
            unsigned mask = __match_any_sync(0xffffffffu, e);
            int prefix = __popc(mask & ((1u << lane) - 1u));
            int base = cnt[w][e];
            __syncwarp();
            int pos = base + prefix;
            g_pos[(b * NT + t) * NKT + k] = pos;
            if (pos < NCAP) g_src[e * NM + b * NCAP + pos] = b * NT + t;
            if (lane == (31 - __clz(mask))) cnt[w][e] = base + __popc(mask);
            __syncwarp();
        }
    }
}

// ---------------------------------------------------------------- mlp1 (HMMA hi/lo, 2-stage smem)
// kstep=16. stage: A_H[128x48B]=6144, A_L=6144, F_H[16x144B]=2304, F_L, G_H, G_L
#define STG1  21504
#define M1_AH 0
#define M1_AL 6144
#define M1_FH 12288
#define M1_FL 14592
#define M1_GH 16896
#define M1_GL 19200

__global__ void __launch_bounds__(256) mlp1_kernel(const float* __restrict__ x,
                                                   const float* __restrict__ bfc,
                                                   const float* __restrict__ bgt) {
    __shared__ __align__(16) unsigned char SM[2 * STG1];   // 43008 B
    __shared__ int s_src[128];
    const uint32_t sb = smem_u32(SM);
    const int tid = threadIdx.x;
    const int e = blockIdx.z;
    const int n0 = blockIdx.x * 64, m0 = blockIdx.y * 128;

    if (tid < 128) s_src[tid] = g_src[e * NM + m0 + tid];
    __syncthreads();

    const __nv_bfloat16* Wfh = (const __nv_bfloat16*)g_u + 0 * WSZ + (size_t)e * NC * NH;
    const __nv_bfloat16* Wfl = (const __nv_bfloat16*)g_u + 1 * WSZ + (size_t)e * NC * NH;
    const __nv_bfloat16* Wgh = (const __nv_bfloat16*)g_u + 2 * WSZ + (size_t)e * NC * NH;
    const __nv_bfloat16* Wgl = (const __nv_bfloat16*)g_u + 3 * WSZ + (size_t)e * NC * NH;

    const int wid = tid >> 5, lane = tid & 31;
    const int mwarp = wid >> 1, nwarp = wid & 1;
    const uint32_t a_off = (uint32_t)(mwarp * 32 + (lane & 15)) * 48 + ((lane & 16) ? 16 : 0);
    const uint32_t bt_off = (uint32_t)(lane & 15) * 144 + ((lane & 16) ? 16 : 0) + nwarp * 64;

    float acch[2][4][4] = {};
    float accg[2][4][4] = {};

    // prefetch registers
    float4 pA[2];
    uint2 pFh, pFl, pGh, pGl;
    const int r2 = tid >> 4, ch2 = tid & 15;

    auto ld_stage = [&](int s) {
        const int k0 = s * 16;
        #pragma unroll
        for (int i = 0; i < 2; i++) {
            int j = tid + i * 256;
            int r = j >> 2, ch = j & 3;
            int srow = s_src[r];
            pA[i] = (srow >= 0)
                ? *(const float4*)(x + (size_t)srow * NC + k0 + ch * 4)
                : make_float4(0.f, 0.f, 0.f, 0.f);
        }
        size_t goff = (size_t)(k0 + r2) * NH + n0 + ch2 * 4;
        pFh = *(const uint2*)(Wfh + goff);
        pFl = *(const uint2*)(Wfl + goff);
        pGh = *(const uint2*)(Wgh + goff);
        pGl = *(const uint2*)(Wgl + goff);
    };
    auto st_stage = [&](int buf) {
        const uint32_t base = buf * STG1;
        #pragma unroll
        for (int i = 0; i < 2; i++) {
            int j = tid + i * 256;
            int r = j >> 2, ch = j & 3;
            uint2 h, l;
            split4(pA[i], h, l);
            uint32_t d = base + (uint32_t)r * 48 + ch * 8;
            *(uint2*)(SM + M1_AH + d) = h;
            *(uint2*)(SM + M1_AL + d) = l;
        }
        uint32_t d2 = base + (uint32_t)r2 * 144 + ch2 * 8;
        *(uint2*)(SM + M1_FH + d2) = pFh;
        *(uint2*)(SM + M1_FL + d2) = pFl;
        *(uint2*)(SM + M1_GH + d2) = pGh;
        *(uint2*)(SM + M1_GL + d2) = pGl;
    };

    const int NS = NC / 16;   // 48
    ld_stage(0);
    for (int s = 0; s < NS; s++) {
        const int buf = s & 1;
        st_stage(buf);               // safe: all warps past sync(s-1) => compute(s-2) done
        __syncthreads();
        if (s + 1 < NS) ld_stage(s + 1);   // LDG in flight during compute
        const uint32_t base = sb + buf * STG1;

        uint32_t ah[2][4], al[2][4];
        #pragma unroll
        for (int mt = 0; mt < 2; mt++) {
            ldsm4(ah[mt], base + M1_AH + a_off + mt * 768);
            ldsm4(al[mt], base + M1_AL + a_off + mt * 768);
        }
        uint32_t fh[2][4], fl[2][4], gh[2][4], gl[2][4];
        #pragma unroll
        for (int q = 0; q < 2; q++) {
            uint32_t bo = bt_off + q * 32;
            ldsm4t(fh[q], base + M1_FH + bo);
            ldsm4t(fl[q], base + M1_FL + bo);
            ldsm4t(gh[q], base + M1_GH + bo);
            ldsm4t(gl[q], base + M1_GL + bo);
        }
        #pragma unroll
        for (int mt = 0; mt < 2; mt++)
            #pragma unroll
            for (int nt = 0; nt < 4; nt++) {
                const uint32_t* FH = &fh[nt >> 1][(nt & 1) * 2];
                const uint32_t* FL = &fl[nt >> 1][(nt & 1) * 2];
                const uint32_t* GH = &gh[nt >> 1][(nt & 1) * 2];
                const uint32_t* GL = &gl[nt >> 1][(nt & 1) * 2];
                mma_bf16(acch[mt][nt], ah[mt], FH);
                mma_bf16(acch[mt][nt], al[mt], FH);
                mma_bf16(acch[mt][nt], ah[mt], FL);
                mma_bf16(accg[mt][nt], ah[mt], GH);
                mma_bf16(accg[mt][nt], al[mt], GH);
                mma_bf16(accg[mt][nt], ah[mt], GL);
            }
    }

    // epilogue: silu(h*g) -> bf16 hi/lo activations
    const int qr = lane >> 2, qc = (lane & 3) * 2;
    #pragma unroll
    for (int mt = 0; mt < 2; mt++) {
        #pragma unroll
        for (int nt = 0; nt < 4; nt++) {
            const int col = n0 + nwarp * 32 + nt * 8 + qc;
            const float b0 = bfc[e * NH + col], b1 = bfc[e * NH + col + 1];
            const float c0 = bgt[e * NH + col], c1 = bgt[e * NH + col + 1];
            #pragma unroll
            for (int hf = 0; hf < 2; hf++) {
                const int row = m0 + mwarp * 32 + mt * 16 + qr + hf * 8;
                float h0 = acch[mt][nt][hf * 2 + 0] + b0;
                float h1 = acch[mt][nt][hf * 2 + 1] + b1;
                float g0 = accg[mt][nt][hf * 2 + 0] + c0;
                float g1 = accg[mt][nt][hf * 2 + 1] + c1;
                float z0 = h0 * g0, z1 = h1 * g1;
                float v0 = z0 / (1.f + expf(-z0));
                float v1 = z1 / (1.f + expf(-z1));
                __nv_bfloat16 H0 = __float2bfloat16(v0), H1 = __float2bfloat16(v1);
                float r0 = v0 - __bfloat162float(H0);
                float r1 = v1 - __bfloat162float(H1);
                uint32_t hi = (uint32_t)__bfloat16_as_ushort(H0)
                            | ((uint32_t)__bfloat16_as_ushort(H1) << 16);
                uint32_t lo = (uint32_t)__bfloat16_as_ushort(__float2bfloat16(r0))
                            | ((uint32_t)__bfloat16_as_ushort(__float2bfloat16(r1)) << 16);
                size_t off = ((size_t)(e * NM + row)) * NH + col;
                *(uint32_t*)(g_acth + off) = hi;
                *(uint32_t*)(g_actl + off) = lo;
            }
        }
    }
}

// ---------------------------------------------------------------- mlp2 (HMMA hi/lo, 2-stage smem)
#define STG2  16896
#define M2_AH 0
#define M2_AL 6144
#define M2_BH 12288
#define M2_BL 14592

__global__ void __launch_bounds__(256) mlp2_kernel(const float* __restrict__ wp,
                                                   const float* __restrict__ bp) {
    __shared__ __align__(16) unsigned char SM[2 * STG2];   // 33792 B
    const uint32_t sb = smem_u32(SM);
    const int tid = threadIdx.x;
    const int e = blockIdx.z;
    const int n0 = blockIdx.x * 64, m0 = blockIdx.y * 128;

    const __nv_bfloat16* Ah = g_acth + ((size_t)e * NM + m0) * NH;
    const __nv_bfloat16* Al = g_actl + ((size_t)e * NM + m0) * NH;
    const float* W = wp + (size_t)e * NH * NC;   // [K=3072][N=768]
    float* g_o = (float*)g_u;                    // reuse union buffer (mlp1 weights dead)

    const int wid = tid >> 5, lane = tid & 31;
    const int mwarp = wid >> 1, nwarp = wid & 1;
    const uint32_t a_off = (uint32_t)(mwarp * 32 + (lane & 15)) * 48 + ((lane & 16) ? 16 : 0);
    const uint32_t bt_off = (uint32_t)(lane & 15) * 144 + ((lane & 16) ? 16 : 0) + nwarp * 64;

    float acc[2][4][4] = {};

    uint2 pAh[2], pAl[2];
    float4 pB;
    const int r2 = tid >> 4, ch2 = tid & 15;

    auto ld_stage = [&](int s) {
        const int k0 = s * 16;
        #pragma unroll
        for (int i = 0; i < 2; i++) {
            int j = tid + i * 256;
            int r = j >> 2, ch = j & 3;
            size_t goff = (size_t)r * NH + k0 + ch * 4;
            pAh[i] = *(const uint2*)(Ah + goff);
            pAl[i] = *(const uint2*)(Al + goff);
        }
        pB = *(const float4*)(W + (size_t)(k0 + r2) * NC + n0 + ch2 * 4);
    };
    auto st_stage = [&](int buf) {
        const uint32_t base = buf * STG2;
        #pragma unroll
        for (int i = 0; i < 2; i++) {
            int j = tid + i * 256;
            int r = j >> 2, ch = j & 3;
            uint32_t d = base + (uint32_t)r * 48 + ch * 8;
            *(uint2*)(SM + M2_AH + d) = pAh[i];
            *(uint2*)(SM + M2_AL + d) = pAl[i];
        }
        uint2 h, l;
        split4(pB, h, l);
        uint32_t d2 = base + (uint32_t)r2 * 144 + ch2 * 8;
        *(uint2*)(SM + M2_BH + d2) = h;
        *(uint2*)(SM + M2_BL + d2) = l;
    };

    const int NS = NH / 16;   // 192
    ld_stage(0);
    for (int s = 0; s < NS; s++) {
        const int buf = s & 1;
        st_stage(buf);
        __syncthreads();
        if (s + 1 < NS) ld_stage(s + 1);
        const uint32_t base = sb + buf * STG2;

        uint32_t ah[2][4], al[2][4];
        #pragma unroll
        for (int mt = 0; mt < 2; mt++) {
            ldsm4(ah[mt], base + M2_AH + a_off + mt * 768);
            ldsm4(al[mt], base + M2_AL + a_off + mt * 768);
        }
        uint32_t bh[2][4], bl[2][4];
        #pragma unroll
        for (int q = 0; q < 2; q++) {
            uint32_t bo = bt_off + q * 32;
            ldsm4t(bh[q], base + M2_BH + bo);
            ldsm4t(bl[q], base + M2_BL + bo);
        }
        #pragma unroll
        for (int mt = 0; mt < 2; mt++)
            #pragma unroll
            for (int nt = 0; nt < 4; nt++) {
                const uint32_t* BH = &bh[nt >> 1][(nt & 1) * 2];
                const uint32_t* BL = &bl[nt >> 1][(nt & 1) * 2];
                mma_bf16(acc[mt][nt], ah[mt], BH);
                mma_bf16(acc[mt][nt], al[mt], BH);
                mma_bf16(acc[mt][nt], ah[mt], BL);
            }
    }

    const int qr = lane >> 2, qc = (lane & 3) * 2;
    #pragma unroll
    for (int mt = 0; mt < 2; mt++) {
        #pragma unroll
        for (int nt = 0; nt < 4; nt++) {
            const int col = n0 + nwarp * 32 + nt * 8 + qc;
            const float b0 = bp[e * NC + col], b1 = bp[e * NC + col + 1];
            #pragma unroll
            for (int hf = 0; hf < 2; hf++) {
                const int row = m0 + mwarp * 32 + mt * 16 + qr + hf * 8;
                float2 o;
                o.x = acc[mt][nt][hf * 2 + 0] + b0;
                o.y = acc[mt][nt][hf * 2 + 1] + b1;
                *(float2*)(g_o + ((size_t)(e * NM + row)) * NC + col) = o;
            }
        }
    }
}

// ---------------------------------------------------------------- combine (reads g_o from union)
__global__ void combine_kernel(float* __restrict__ out) {
    const float* g_o = (const float*)g_u;
    int token = blockIdx.x;
    int b = token / NT;

    int e0 = g_ei[token * 2 + 0], e1 = g_ei[token * 2 + 1];
    float p0 = g_p[token * 2 + 0], p1 = g_p[token * 2 + 1];
    int q0 = min(g_pos[token * 2 + 0], NCAP - 1);
    int q1 = min(g_pos[token * 2 + 1], NCAP - 1);

    const float4* r0 = (const float4*)(g_o + ((size_t)e0 * NM + b * NCAP + q0) * NC);
    const float4* r1 = (const float4*)(g_o + ((size_t)e1 * NM + b * NCAP + q1) * NC);

    int c = threadIdx.x;
    float4 v0 = r0[c], v1 = r1[c];
    float4 o;
    o.x = p0 * v0.x + p1 * v1.x;
    o.y = p0 * v0.y + p1 * v1.y;
    o.z = p0 * v0.z + p1 * v1.z;
    o.w = p0 * v0.w + p1 * v1.w;
    ((float4*)out)[(size_t)token * (NC / 4) + c] = o;
}

// ---------------------------------------------------------------- launch
extern "C" void kernel_launch(void* const* d_in, const int* in_sizes, int n_in,
                              void* d_out, int out_size) {
    const float* x        = (const float*)d_in[0];
    const float* w_router = (const float*)d_in[1];
    const float* b_router = (const float*)d_in[2];
    const float* w_c_fc   = (const float*)d_in[3];
    const float* b_c_fc   = (const float*)d_in[4];
    const float* w_gate   = (const float*)d_in[5];
    const float* b_gate   = (const float*)d_in[6];
    const float* w_c_proj = (const float*)d_in[7];
    const float* b_c_proj = (const float*)d_in[8];
    float* out = (float*)d_out;

    __nv_bfloat16* gu = nullptr;
    cudaGetSymbolAddress((void**)&gu, g_u);

    const int W4 = (int)(WSZ / 4);   // float4 count per weight tensor
    wsplit_kernel<<<W4 / 256, 256>>>(w_c_fc, gu + 0 * WSZ, gu + 1 * WSZ);
    wsplit_kernel<<<W4 / 256, 256>>>(w_gate, gu + 2 * WSZ, gu + 3 * WSZ);

    router_kernel<<<NB * NT / 8, 256>>>(x, w_router, b_router);
    fill_src_kernel<<<(NE * NM + 255) / 256, 256>>>();
    pos_kernel<<<1, 256>>>();

    mlp1_kernel<<<dim3(NH / 64, NM / 128, NE), 256>>>(x, b_c_fc, b_gate);
    mlp2_kernel<<<dim3(NC / 64, NM / 128, NE), 256>>>(w_c_proj, b_c_proj);

    combine_kernel<<<NB * NT, 192>>>(out);
}

// round 10
// speedup vs baseline: 2.8181x; 1.1426x over previous
#include <cuda_runtime.h>
#include <cuda_bf16.h>
#include <math.h>
#include <stdint.h>

// ---------------------------------------------------------------- dims
#define NB   8
#define NT   2048
#define NC   768
#define NE   8
#define NKT  2
#define NH   3072
#define NCAP 640
#define NM   (NB * NCAP)   // 5120 rows per expert
#define WSZ  ((size_t)NE * NC * NH)   // elements per weight tensor

// ---------------------------------------------------------------- helpers
__device__ __forceinline__ uint32_t smem_u32(const void* p) {
    uint32_t a;
    asm("{ .reg .u64 t; cvta.to.shared.u64 t, %1; cvt.u32.u64 %0, t; }"
        : "=r"(a) : "l"(p));
    return a;
}
__device__ __forceinline__ void ldsm4(uint32_t* r, uint32_t a) {
    asm volatile("ldmatrix.sync.aligned.m8n8.x4.shared.b16 {%0,%1,%2,%3}, [%4];"
        : "=r"(r[0]), "=r"(r[1]), "=r"(r[2]), "=r"(r[3]) : "r"(a));
}
__device__ __forceinline__ void ldsm4t(uint32_t* r, uint32_t a) {
    asm volatile("ldmatrix.sync.aligned.m8n8.x4.trans.shared.b16 {%0,%1,%2,%3}, [%4];"
        : "=r"(r[0]), "=r"(r[1]), "=r"(r[2]), "=r"(r[3]) : "r"(a));
}
__device__ __forceinline__ void mma_bf16(float* d, const uint32_t* a, const uint32_t* b) {
    asm volatile(
        "mma.sync.aligned.m16n8k16.row.col.f32.bf16.bf16.f32 "
        "{%0,%1,%2,%3}, {%4,%5,%6,%7}, {%8,%9}, {%0,%1,%2,%3};"
        : "+f"(d[0]), "+f"(d[1]), "+f"(d[2]), "+f"(d[3])
        : "r"(a[0]), "r"(a[1]), "r"(a[2]), "r"(a[3]), "r"(b[0]), "r"(b[1]));
}
// split float4 into packed bf16 hi (uint2) and lo residual (uint2)
__device__ __forceinline__ void split4(float4 v, uint2& h, uint2& l) {
    __nv_bfloat16 h0 = __float2bfloat16(v.x), h1 = __float2bfloat16(v.y);
    __nv_bfloat16 h2 = __float2bfloat16(v.z), h3 = __float2bfloat16(v.w);
    float r0 = v.x - __bfloat162float(h0), r1 = v.y - __bfloat162float(h1);
    float r2 = v.z - __bfloat162float(h2), r3 = v.w - __bfloat162float(h3);
    h.x = (uint32_t)__bfloat16_as_ushort(h0) | ((uint32_t)__bfloat16_as_ushort(h1) << 16);
    h.y = (uint32_t)__bfloat16_as_ushort(h2) | ((uint32_t)__bfloat16_as_ushort(h3) << 16);
    l.x = (uint32_t)__bfloat16_as_ushort(__float2bfloat16(r0))
        | ((uint32_t)__bfloat16_as_ushort(__float2bfloat16(r1)) << 16);
    l.y = (uint32_t)__bfloat16_as_ushort(__float2bfloat16(r2))
        | ((uint32_t)__bfloat16_as_ushort(__float2bfloat16(r3)) << 16);
}

// ---------------------------------------------------------------- scratch (≈654MB total)
__device__ __nv_bfloat16 g_acth[(size_t)NE * NM * NH];  // activation hi (252MB)
__device__ __nv_bfloat16 g_actl[(size_t)NE * NM * NH];  // activation lo (252MB)
// union buffer (151MB): phase 1 = fc/gate weight splits (wsplit + mlp1),
// phase 2 = g_o fp32 expert outputs (mlp2 + combine).
__device__ __align__(1024) unsigned char g_u[4 * WSZ * 2];
__device__ float g_p  [NB * NT * NKT];
__device__ int   g_ei [NB * NT * NKT];
__device__ int   g_pos[NB * NT * NKT];
__device__ int   g_src[NE * NM];

// ---------------------------------------------------------------- prep: elementwise hi/lo split
__global__ void wsplit_kernel(const float* __restrict__ in,
                              __nv_bfloat16* __restrict__ oh,
                              __nv_bfloat16* __restrict__ ol) {
    size_t i = (size_t)blockIdx.x * 256 + threadIdx.x;   // float4 index
    float4 v = ((const float4*)in)[i];
    uint2 h, l;
    split4(v, h, l);
    ((uint2*)oh)[i] = h;
    ((uint2*)ol)[i] = l;
}

// ---------------------------------------------------------------- router (unchanged, passing)
__global__ void router_kernel(const float* __restrict__ x,
                              const float* __restrict__ wr,
                              const float* __restrict__ br) {
    __shared__ float ws[NC * NE];
    int tid = threadIdx.x;
    const float4* wr4 = (const float4*)wr;
    float4* ws4 = (float4*)ws;
    #pragma unroll
    for (int i = tid; i < NC * NE / 4; i += 256) ws4[i] = wr4[i];
    __syncthreads();

    int warp = tid >> 5, lane = tid & 31;
    int token = blockIdx.x * 8 + warp;
    const float* xrow = x + (size_t)token * NC;

    float acc[NE];
    #pragma unroll
    for (int e = 0; e < NE; e++) acc[e] = 0.f;
    for (int c = lane; c < NC; c += 32) {
        float xv = xrow[c];
        #pragma unroll
        for (int e = 0; e < NE; e++) acc[e] = fmaf(xv, ws[c * NE + e], acc[e]);
    }
    #pragma unroll
    for (int e = 0; e < NE; e++) {
        #pragma unroll
        for (int off = 16; off; off >>= 1)
            acc[e] += __shfl_xor_sync(0xffffffffu, acc[e], off);
    }
    if (lane == 0) {
        float l[NE], p[NE];
        float mx = -1e30f;
        #pragma unroll
        for (int e = 0; e < NE; e++) { l[e] = acc[e] + br[e]; mx = fmaxf(mx, l[e]); }
        float s = 0.f;
        #pragma unroll
        for (int e = 0; e < NE; e++) { p[e] = expf(l[e] - mx); s += p[e]; }
        float inv = 1.f / s;
        #pragma unroll
        for (int e = 0; e < NE; e++) p[e] *= inv;

        int i1 = 0; float p1 = p[0];
        #pragma unroll
        for (int e = 1; e < NE; e++) if (p[e] > p1) { p1 = p[e]; i1 = e; }
        int i2 = -1; float p2 = -1.f;
        #pragma unroll
        for (int e = 0; e < NE; e++) if (e != i1 && p[e] > p2) { p2 = p[e]; i2 = e; }

        g_p [token * 2 + 0] = p1;  g_p [token * 2 + 1] = p2;
        g_ei[token * 2 + 0] = i1;  g_ei[token * 2 + 1] = i2;
    }
}

__global__ void fill_src_kernel() {
    int i = blockIdx.x * 256 + threadIdx.x;
    if (i < NE * NM) g_src[i] = -1;
}

// capacity scan, exact k-major cumsum order per batch (unchanged, passing)
__global__ void pos_kernel() {
    __shared__ int cnt[8][NE];
    int w = threadIdx.x >> 5, lane = threadIdx.x & 31;
    int b = w;
    if (lane < NE) cnt[w][lane] = 0;
    __syncwarp();
    for (int k = 0; k < NKT; k++) {
        for (int t0 = 0; t0 < NT; t0 += 32) {
            int t = t0 + lane;
            int e = g_ei[(b * NT + t) * NKT + k];
            unsigned mask = __match_any_sync(0xffffffffu, e);
            int prefix = __popc(mask & ((1u << lane) - 1u));
            int base = cnt[w][e];
            __syncwarp();
            int pos = base + prefix;
            g_pos[(b * NT + t) * NKT + k] = pos;
            if (pos < NCAP) g_src[e * NM + b * NCAP + pos] = b * NT + t;
            if (lane == (31 - __clz(mask))) cnt[w][e] = base + __popc(mask);
            __syncwarp();
        }
    }
}

// ---------------------------------------------------------------- mlp1 (HMMA hi/lo, 2-stage smem)
// grid: x = m-tiles (fastest) so all m-CTAs of one n-column run concurrently
// and share the same weight tile in L2 -> weights stream from DRAM ~once.
#define STG1  21504
#define M1_AH 0
#define M1_AL 6144
#define M1_FH 12288
#define M1_FL 14592
#define M1_GH 16896
#define M1_GL 19200

__global__ void __launch_bounds__(256) mlp1_kernel(const float* __restrict__ x,
                                                   const float* __restrict__ bfc,
                                                   const float* __restrict__ bgt) {
    __shared__ __align__(16) unsigned char SM[2 * STG1];   // 43008 B
    __shared__ int s_src[128];
    const uint32_t sb = smem_u32(SM);
    const int tid = threadIdx.x;
    const int e = blockIdx.z;
    const int m0 = blockIdx.x * 128, n0 = blockIdx.y * 64;   // m fastest

    if (tid < 128) s_src[tid] = g_src[e * NM + m0 + tid];
    __syncthreads();

    const __nv_bfloat16* Wfh = (const __nv_bfloat16*)g_u + 0 * WSZ + (size_t)e * NC * NH;
    const __nv_bfloat16* Wfl = (const __nv_bfloat16*)g_u + 1 * WSZ + (size_t)e * NC * NH;
    const __nv_bfloat16* Wgh = (const __nv_bfloat16*)g_u + 2 * WSZ + (size_t)e * NC * NH;
    const __nv_bfloat16* Wgl = (const __nv_bfloat16*)g_u + 3 * WSZ + (size_t)e * NC * NH;

    const int wid = tid >> 5, lane = tid & 31;
    const int mwarp = wid >> 1, nwarp = wid & 1;
    const uint32_t a_off = (uint32_t)(mwarp * 32 + (lane & 15)) * 48 + ((lane & 16) ? 16 : 0);
    const uint32_t bt_off = (uint32_t)(lane & 15) * 144 + ((lane & 16) ? 16 : 0) + nwarp * 64;

    float acch[2][4][4] = {};
    float accg[2][4][4] = {};

    // prefetch registers
    float4 pA[2];
    uint2 pFh, pFl, pGh, pGl;
    const int r2 = tid >> 4, ch2 = tid & 15;

    auto ld_stage = [&](int s) {
        const int k0 = s * 16;
        #pragma unroll
        for (int i = 0; i < 2; i++) {
            int j = tid + i * 256;
            int r = j >> 2, ch = j & 3;
            int srow = s_src[r];
            pA[i] = (srow >= 0)
                ? *(const float4*)(x + (size_t)srow * NC + k0 + ch * 4)
                : make_float4(0.f, 0.f, 0.f, 0.f);
        }
        size_t goff = (size_t)(k0 + r2) * NH + n0 + ch2 * 4;
        pFh = *(const uint2*)(Wfh + goff);
        pFl = *(const uint2*)(Wfl + goff);
        pGh = *(const uint2*)(Wgh + goff);
        pGl = *(const uint2*)(Wgl + goff);
    };
    auto st_stage = [&](int buf) {
        const uint32_t base = buf * STG1;
        #pragma unroll
        for (int i = 0; i < 2; i++) {
            int j = tid + i * 256;
            int r = j >> 2, ch = j & 3;
            uint2 h, l;
            split4(pA[i], h, l);
            uint32_t d = base + (uint32_t)r * 48 + ch * 8;
            *(uint2*)(SM + M1_AH + d) = h;
            *(uint2*)(SM + M1_AL + d) = l;
        }
        uint32_t d2 = base + (uint32_t)r2 * 144 + ch2 * 8;
        *(uint2*)(SM + M1_FH + d2) = pFh;
        *(uint2*)(SM + M1_FL + d2) = pFl;
        *(uint2*)(SM + M1_GH + d2) = pGh;
        *(uint2*)(SM + M1_GL + d2) = pGl;
    };

    const int NS = NC / 16;   // 48
    ld_stage(0);
    for (int s = 0; s < NS; s++) {
        const int buf = s & 1;
        st_stage(buf);
        __syncthreads();
        if (s + 1 < NS) ld_stage(s + 1);
        const uint32_t base = sb + buf * STG1;

        uint32_t ah[2][4], al[2][4];
        #pragma unroll
        for (int mt = 0; mt < 2; mt++) {
            ldsm4(ah[mt], base + M1_AH + a_off + mt * 768);
            ldsm4(al[mt], base + M1_AL + a_off + mt * 768);
        }
        uint32_t fh[2][4], fl[2][4], gh[2][4], gl[2][4];
        #pragma unroll
        for (int q = 0; q < 2; q++) {
            uint32_t bo = bt_off + q * 32;
            ldsm4t(fh[q], base + M1_FH + bo);
            ldsm4t(fl[q], base + M1_FL + bo);
            ldsm4t(gh[q], base + M1_GH + bo);
            ldsm4t(gl[q], base + M1_GL + bo);
        }
        #pragma unroll
        for (int mt = 0; mt < 2; mt++)
            #pragma unroll
            for (int nt = 0; nt < 4; nt++) {
                const uint32_t* FH = &fh[nt >> 1][(nt & 1) * 2];
                const uint32_t* FL = &fl[nt >> 1][(nt & 1) * 2];
                const uint32_t* GH = &gh[nt >> 1][(nt & 1) * 2];
                const uint32_t* GL = &gl[nt >> 1][(nt & 1) * 2];
                mma_bf16(acch[mt][nt], ah[mt], FH);
                mma_bf16(acch[mt][nt], al[mt], FH);
                mma_bf16(acch[mt][nt], ah[mt], FL);
                mma_bf16(accg[mt][nt], ah[mt], GH);
                mma_bf16(accg[mt][nt], al[mt], GH);
                mma_bf16(accg[mt][nt], ah[mt], GL);
            }
    }

    // epilogue: silu(h*g) -> bf16 hi/lo activations
    const int qr = lane >> 2, qc = (lane & 3) * 2;
    #pragma unroll
    for (int mt = 0; mt < 2; mt++) {
        #pragma unroll
        for (int nt = 0; nt < 4; nt++) {
            const int col = n0 + nwarp * 32 + nt * 8 + qc;
            const float b0 = bfc[e * NH + col], b1 = bfc[e * NH + col + 1];
            const float c0 = bgt[e * NH + col], c1 = bgt[e * NH + col + 1];
            #pragma unroll
            for (int hf = 0; hf < 2; hf++) {
                const int row = m0 + mwarp * 32 + mt * 16 + qr + hf * 8;
                float h0 = acch[mt][nt][hf * 2 + 0] + b0;
                float h1 = acch[mt][nt][hf * 2 + 1] + b1;
                float g0 = accg[mt][nt][hf * 2 + 0] + c0;
                float g1 = accg[mt][nt][hf * 2 + 1] + c1;
                float z0 = h0 * g0, z1 = h1 * g1;
                float v0 = z0 / (1.f + expf(-z0));
                float v1 = z1 / (1.f + expf(-z1));
                __nv_bfloat16 H0 = __float2bfloat16(v0), H1 = __float2bfloat16(v1);
                float r0 = v0 - __bfloat162float(H0);
                float r1 = v1 - __bfloat162float(H1);
                uint32_t hi = (uint32_t)__bfloat16_as_ushort(H0)
                            | ((uint32_t)__bfloat16_as_ushort(H1) << 16);
                uint32_t lo = (uint32_t)__bfloat16_as_ushort(__float2bfloat16(r0))
                            | ((uint32_t)__bfloat16_as_ushort(__float2bfloat16(r1)) << 16);
                size_t off = ((size_t)(e * NM + row)) * NH + col;
                *(uint32_t*)(g_acth + off) = hi;
                *(uint32_t*)(g_actl + off) = lo;
            }
        }
    }
}

// ---------------------------------------------------------------- mlp2 (HMMA hi/lo, CTA 128x128)
// kstep=16. stage: A_H[128x48B]=6144, A_L=6144, B_H[16x272B]=4352, B_L=4352
#define STG2  20992
#define M2_AH 0
#define M2_AL 6144
#define M2_BH 12288
#define M2_BL 16640

__global__ void __launch_bounds__(256) mlp2_kernel(const float* __restrict__ wp,
                                                   const float* __restrict__ bp) {
    __shared__ __align__(16) unsigned char SM[2 * STG2];   // 41984 B
    const uint32_t sb = smem_u32(SM);
    const int tid = threadIdx.x;
    const int e = blockIdx.z;
    const int n0 = blockIdx.x * 128, m0 = blockIdx.y * 128;

    const __nv_bfloat16* Ah = g_acth + ((size_t)e * NM + m0) * NH;
    const __nv_bfloat16* Al = g_actl + ((size_t)e * NM + m0) * NH;
    const float* W = wp + (size_t)e * NH * NC;   // [K=3072][N=768]
    float* g_o = (float*)g_u;                    // reuse union buffer

    const int wid = tid >> 5, lane = tid & 31;
    const int mwarp = wid >> 1, nwarp = wid & 1;   // warp tile 32 x 64
    const uint32_t a_off = (uint32_t)(mwarp * 32 + (lane & 15)) * 48 + ((lane & 16) ? 16 : 0);
    const uint32_t bt_off = (uint32_t)(lane & 15) * 272 + ((lane & 16) ? 16 : 0) + nwarp * 128;

    float acc[2][8][4] = {};

    uint2 pAh[2], pAl[2];
    float4 pB[2];

    auto ld_stage = [&](int s) {
        const int k0 = s * 16;
        #pragma unroll
        for (int i = 0; i < 2; i++) {
            int j = tid + i * 256;
            int r = j >> 2, ch = j & 3;
            size_t goff = (size_t)r * NH + k0 + ch * 4;
            pAh[i] = *(const uint2*)(Ah + goff);
            pAl[i] = *(const uint2*)(Al + goff);
        }
        #pragma unroll
        for (int i = 0; i < 2; i++) {
            int j = tid + i * 256;
            int r = j >> 5, ch = j & 31;   // 16 k-rows x 32 float4 chunks
            pB[i] = *(const float4*)(W + (size_t)(k0 + r) * NC + n0 + ch * 4);
        }
    };
    auto st_stage = [&](int buf) {
        const uint32_t base = buf * STG2;
        #pragma unroll
        for (int i = 0; i < 2; i++) {
            int j = tid + i * 256;
            int r = j >> 2, ch = j & 3;
            uint32_t d = base + (uint32_t)r * 48 + ch * 8;
            *(uint2*)(SM + M2_AH + d) = pAh[i];
            *(uint2*)(SM + M2_AL + d) = pAl[i];
        }
        #pragma unroll
        for (int i = 0; i < 2; i++) {
            int j = tid + i * 256;
            int r = j >> 5, ch = j & 31;
            uint2 h, l;
            split4(pB[i], h, l);
            uint32_t d = base + (uint32_t)r * 272 + ch * 8;
            *(uint2*)(SM + M2_BH + d) = h;
            *(uint2*)(SM + M2_BL + d) = l;
        }
    };

    const int NS = NH / 16;   // 192
    ld_stage(0);
    for (int s = 0; s < NS; s++) {
        const int buf = s & 1;
        st_stage(buf);
        __syncthreads();
        if (s + 1 < NS) ld_stage(s + 1);
        const uint32_t base = sb + buf * STG2;

        uint32_t ah[2][4], al[2][4];
        #pragma unroll
        for (int mt = 0; mt < 2; mt++) {
            ldsm4(ah[mt], base + M2_AH + a_off + mt * 768);
            ldsm4(al[mt], base + M2_AL + a_off + mt * 768);
        }
        uint32_t bh[4][4], bl[4][4];
        #pragma unroll
        for (int q = 0; q < 4; q++) {
            uint32_t bo = bt_off + q * 32;   // 16 n-cols per x4.trans (FIXED: was q*64 OOB)
            ldsm4t(bh[q], base + M2_BH + bo);
            ldsm4t(bl[q], base + M2_BL + bo);
        }
        #pragma unroll
        for (int mt = 0; mt < 2; mt++)
            #pragma unroll
            for (int nt = 0; nt < 8; nt++) {
                const uint32_t* BH = &bh[nt >> 1][(nt & 1) * 2];
                const uint32_t* BL = &bl[nt >> 1][(nt & 1) * 2];
                mma_bf16(acc[mt][nt], ah[mt], BH);
                mma_bf16(acc[mt][nt], al[mt], BH);
                mma_bf16(acc[mt][nt], ah[mt], BL);
            }
    }

    const int qr = lane >> 2, qc = (lane & 3) * 2;
    #pragma unroll
    for (int mt = 0; mt < 2; mt++) {
        #pragma unroll
        for (int nt = 0; nt < 8; nt++) {
            const int col = n0 + nwarp * 64 + nt * 8 + qc;
            const float b0 = bp[e * NC + col], b1 = bp[e * NC + col + 1];
            #pragma unroll
            for (int hf = 0; hf < 2; hf++) {
                const int row = m0 + mwarp * 32 + mt * 16 + qr + hf * 8;
                float2 o;
                o.x = acc[mt][nt][hf * 2 + 0] + b0;
                o.y = acc[mt][nt][hf * 2 + 1] + b1;
                *(float2*)(g_o + ((size_t)(e * NM + row)) * NC + col) = o;
            }
        }
    }
}

// ---------------------------------------------------------------- combine (reads g_o from union)
__global__ void combine_kernel(float* __restrict__ out) {
    const float* g_o = (const float*)g_u;
    int token = blockIdx.x;
    int b = token / NT;

    int e0 = g_ei[token * 2 + 0], e1 = g_ei[token * 2 + 1];
    float p0 = g_p[token * 2 + 0], p1 = g_p[token * 2 + 1];
    int q0 = min(g_pos[token * 2 + 0], NCAP - 1);
    int q1 = min(g_pos[token * 2 + 1], NCAP - 1);

    const float4* r0 = (const float4*)(g_o + ((size_t)e0 * NM + b * NCAP + q0) * NC);
    const float4* r1 = (const float4*)(g_o + ((size_t)e1 * NM + b * NCAP + q1) * NC);

    int c = threadIdx.x;
    float4 v0 = r0[c], v1 = r1[c];
    float4 o;
    o.x = p0 * v0.x + p1 * v1.x;
    o.y = p0 * v0.y + p1 * v1.y;
    o.z = p0 * v0.z + p1 * v1.z;
    o.w = p0 * v0.w + p1 * v1.w;
    ((float4*)out)[(size_t)token * (NC / 4) + c] = o;
}

// ---------------------------------------------------------------- launch
extern "C" void kernel_launch(void* const* d_in, const int* in_sizes, int n_in,
                              void* d_out, int out_size) {
    const float* x        = (const float*)d_in[0];
    const float* w_router = (const float*)d_in[1];
    const float* b_router = (const float*)d_in[2];
    const float* w_c_fc   = (const float*)d_in[3];
    const float* b_c_fc   = (const float*)d_in[4];
    const float* w_gate   = (const float*)d_in[5];
    const float* b_gate   = (const float*)d_in[6];
    const float* w_c_proj = (const float*)d_in[7];
    const float* b_c_proj = (const float*)d_in[8];
    float* out = (float*)d_out;

    __nv_bfloat16* gu = nullptr;
    cudaGetSymbolAddress((void**)&gu, g_u);

    const int W4 = (int)(WSZ / 4);   // float4 count per weight tensor
    wsplit_kernel<<<W4 / 256, 256>>>(w_c_fc, gu + 0 * WSZ, gu + 1 * WSZ);
    wsplit_kernel<<<W4 / 256, 256>>>(w_gate, gu + 2 * WSZ, gu + 3 * WSZ);

    router_kernel<<<NB * NT / 8, 256>>>(x, w_router, b_router);
    fill_src_kernel<<<(NE * NM + 255) / 256, 256>>>();
    pos_kernel<<<1, 256>>>();

    mlp1_kernel<<<dim3(NM / 128, NH / 64, NE), 256>>>(x, b_c_fc, b_gate);
    mlp2_kernel<<<dim3(NC / 128, NM / 128, NE), 256>>>(w_c_proj, b_c_proj);

    combine_kernel<<<NB * NT, 192>>>(out);
}